// round 4
// baseline (speedup 1.0000x reference)
#include <cuda_runtime.h>
#include <cuda_bf16.h>
#include <math.h>

// Problem constants (fixed by the reference setup)
#define Bz   4
#define NTOK 5440            // 64*64 + 32*32 + 16*16 + 8*8
#define Dm   256
#define FFm  1024
#define NHh  8
#define NLl  4
#define NPp  4
#define DHd  32
#define Mrow (Bz * NTOK)     // 21760

// ---------------------------------------------------------------------------
// Scratch (device globals; no allocations allowed)
// ---------------------------------------------------------------------------
__device__ float g_q[Mrow * Dm];        // src + pos
__device__ float g_value[Mrow * Dm];    // value projection (masked)
__device__ float g_off[Mrow * 256];     // sampling offsets (NH*NL*NP*2 = 256)
__device__ float g_logits[Mrow * 128];  // attention logits (NH*NL*NP = 128)
__device__ float g_a[Mrow * Dm];        // msdeform output
__device__ float g_res[Mrow * Dm];      // pre-LN residual buffer (reused)
__device__ float g_x[Mrow * Dm];        // after LN1
__device__ float g_h[Mrow * FFm];       // FFN hidden

// ---------------------------------------------------------------------------
// Elementwise: q = src + pos
// ---------------------------------------------------------------------------
__global__ void add_kernel(const float* __restrict__ a, const float* __restrict__ b,
                           float* __restrict__ c, int n) {
    int i = blockIdx.x * blockDim.x + threadIdx.x;
    if (i < n) c[i] = a[i] + b[i];
}

// ---------------------------------------------------------------------------
// SGEMM (NT): C[M,N] = A[M,K] @ W[N,K]^T + bias, with fused epilogues.
// BM=BN=64, BK=16, 256 threads, 4x4 microtile. M%64==0, N%64==0, K%16==0.
// EPI: 0=plain  1=relu  2=zero-where-mask  3=add residual R[M,N]
// ---------------------------------------------------------------------------
template <int EPI>
__global__ __launch_bounds__(256)
void sgemm_nt(const float* __restrict__ A, const float* __restrict__ W,
              const float* __restrict__ bias, const float* __restrict__ R,
              const unsigned char* __restrict__ mask,
              float* __restrict__ C, int M, int N, int K) {
    constexpr int BM = 64, BN = 64, BK = 16;
    __shared__ float As[BK][BM];
    __shared__ float Ws[BK][BN];

    const int bm = blockIdx.y * BM;
    const int bn = blockIdx.x * BN;
    const int tid = threadIdx.x;
    const int tx = tid & 15;        // 0..15 -> 4 cols each
    const int ty = tid >> 4;        // 0..15 -> 4 rows each

    float acc[4][4];
#pragma unroll
    for (int i = 0; i < 4; i++)
#pragma unroll
        for (int j = 0; j < 4; j++) acc[i][j] = 0.f;

    for (int k0 = 0; k0 < K; k0 += BK) {
#pragma unroll
        for (int i = 0; i < 4; i++) {
            int e = tid + i * 256;      // 0..1023
            int r = e >> 4;             // row within tile
            int kk = e & 15;            // k within tile
            As[kk][r] = A[(size_t)(bm + r) * K + k0 + kk];
            Ws[kk][r] = W[(size_t)(bn + r) * K + k0 + kk];
        }
        __syncthreads();
#pragma unroll
        for (int kk = 0; kk < BK; kk++) {
            float a[4], w[4];
#pragma unroll
            for (int i = 0; i < 4; i++) a[i] = As[kk][ty * 4 + i];
#pragma unroll
            for (int j = 0; j < 4; j++) w[j] = Ws[kk][tx * 4 + j];
#pragma unroll
            for (int i = 0; i < 4; i++)
#pragma unroll
                for (int j = 0; j < 4; j++) acc[i][j] += a[i] * w[j];
        }
        __syncthreads();
    }

#pragma unroll
    for (int i = 0; i < 4; i++) {
        int row = bm + ty * 4 + i;
#pragma unroll
        for (int j = 0; j < 4; j++) {
            int col = bn + tx * 4 + j;
            float v = acc[i][j] + bias[col];
            if (EPI == 1) v = fmaxf(v, 0.f);
            if (EPI == 2) v = mask[row] ? 0.f : v;
            if (EPI == 3) v += R[(size_t)row * N + col];
            C[(size_t)row * N + col] = v;
        }
    }
}

// ---------------------------------------------------------------------------
// Multi-scale deformable attention core.
// Grid: Mrow blocks (one per (b, query)). Block: 256 threads = 8 warps,
// warp h handles head h; lane = channel d (DH=32). Softmax over the 16
// (level, point) samples is computed in-warp (lanes 0..15 carry s = lane&15).
// ---------------------------------------------------------------------------
__global__ __launch_bounds__(256)
void msdeform_kernel(const float* __restrict__ value,
                     const float* __restrict__ logits,
                     const float* __restrict__ off,
                     const float* __restrict__ ref,
                     float* __restrict__ out) {
    const int row = blockIdx.x;          // b * NTOK + q
    const int h = threadIdx.x >> 5;
    const int lane = threadIdx.x & 31;
    const int b = row / NTOK;
    const int s = lane & 15;

    // softmax over 16 samples of this head (replicated in both warp halves)
    float logit = logits[(size_t)row * 128 + h * 16 + s];
    float mx = logit;
#pragma unroll
    for (int o = 8; o; o >>= 1) mx = fmaxf(mx, __shfl_xor_sync(0xffffffffu, mx, o));
    float e = expf(logit - mx);
    float sm = e;
#pragma unroll
    for (int o = 8; o; o >>= 1) sm += __shfl_xor_sync(0xffffffffu, sm, o);
    float wn = e / sm;

    // this lane's sample offsets (sample index = s)
    float ox = off[(size_t)row * 256 + (h * 16 + s) * 2 + 0];
    float oy = off[(size_t)row * 256 + (h * 16 + s) * 2 + 1];

    const int   HWs[4]    = {64, 32, 16, 8};
    const int   starts[4] = {0, 4096, 5120, 5376};

    float acc = 0.f;
#pragma unroll
    for (int s2 = 0; s2 < 16; s2++) {
        const int l = s2 >> 2;
        const int HW = HWs[l];
        const float aw = __shfl_sync(0xffffffffu, wn, s2);
        const float sx = __shfl_sync(0xffffffffu, ox, s2);
        const float sy = __shfl_sync(0xffffffffu, oy, s2);

        const float rx = ref[((size_t)row * NLl + l) * 2 + 0];
        const float ry = ref[((size_t)row * NLl + l) * 2 + 1];
        const float invHW = 1.0f / (float)HW;

        // loc = ref + off/normalizer ; pixel = loc*W - 0.5
        const float px = (rx + sx * invHW) * (float)HW - 0.5f;
        const float py = (ry + sy * invHW) * (float)HW - 0.5f;
        const float x0f = floorf(px), y0f = floorf(py);
        const float fx = px - x0f, fy = py - y0f;
        const int x0 = (int)x0f, y0 = (int)y0f;

        float samp = 0.f;
#pragma unroll
        for (int c = 0; c < 4; c++) {
            const int xi = x0 + (c & 1);
            const int yi = y0 + (c >> 1);
            const float w = ((c & 1) ? fx : 1.f - fx) * ((c >> 1) ? fy : 1.f - fy);
            if (xi >= 0 && xi < HW && yi >= 0 && yi < HW) {
                const size_t vrow = (size_t)b * NTOK + starts[l] + yi * HW + xi;
                samp += w * value[(vrow * NHh + h) * DHd + lane];
            }
        }
        acc += aw * samp;
    }
    out[(size_t)row * Dm + h * DHd + lane] = acc;
}

// ---------------------------------------------------------------------------
// LayerNorm over last dim (256). One warp per row, 8 rows per block.
// Input X already contains the residual sum.
// ---------------------------------------------------------------------------
__global__ __launch_bounds__(256)
void ln_kernel(const float* __restrict__ X, const float* __restrict__ g,
               const float* __restrict__ be, float* __restrict__ Y) {
    const int row = blockIdx.x * 8 + (threadIdx.x >> 5);
    const int lane = threadIdx.x & 31;
    const float* x = X + (size_t)row * Dm;

    float v[8];
    float s = 0.f, ss = 0.f;
#pragma unroll
    for (int j = 0; j < 8; j++) {
        v[j] = x[lane + 32 * j];
        s += v[j];
        ss += v[j] * v[j];
    }
#pragma unroll
    for (int o = 16; o; o >>= 1) {
        s  += __shfl_xor_sync(0xffffffffu, s, o);
        ss += __shfl_xor_sync(0xffffffffu, ss, o);
    }
    const float mean = s * (1.0f / 256.0f);
    const float var  = ss * (1.0f / 256.0f) - mean * mean;
    const float rs   = rsqrtf(var + 1e-5f);
#pragma unroll
    for (int j = 0; j < 8; j++) {
        const int c = lane + 32 * j;
        Y[(size_t)row * Dm + c] = (v[j] - mean) * rs * g[c] + be[c];
    }
}

// ---------------------------------------------------------------------------
// Launch
// ---------------------------------------------------------------------------
extern "C" void kernel_launch(void* const* d_in, const int* in_sizes, int n_in,
                              void* d_out, int out_size) {
    const float* src  = (const float*)d_in[0];
    const float* pos  = (const float*)d_in[1];
    const float* ref  = (const float*)d_in[2];
    const float* w_value = (const float*)d_in[3];
    const float* b_value = (const float*)d_in[4];
    const float* w_off   = (const float*)d_in[5];
    const float* b_off   = (const float*)d_in[6];
    const float* w_attn  = (const float*)d_in[7];
    const float* b_attn  = (const float*)d_in[8];
    const float* w_out   = (const float*)d_in[9];
    const float* b_out   = (const float*)d_in[10];
    const float* g1  = (const float*)d_in[11];
    const float* be1 = (const float*)d_in[12];
    const float* w1  = (const float*)d_in[13];
    const float* b1  = (const float*)d_in[14];
    const float* w2  = (const float*)d_in[15];
    const float* b2  = (const float*)d_in[16];
    const float* g2  = (const float*)d_in[17];
    const float* be2 = (const float*)d_in[18];
    // d_in[19] spatial_shapes, d_in[20] level_start_index: fixed, hardcoded
    const unsigned char* pad = (const unsigned char*)d_in[21];

    float* out = (float*)d_out;

    float *q, *value, *off, *logits, *a, *res, *x, *h;
    cudaGetSymbolAddress((void**)&q, g_q);
    cudaGetSymbolAddress((void**)&value, g_value);
    cudaGetSymbolAddress((void**)&off, g_off);
    cudaGetSymbolAddress((void**)&logits, g_logits);
    cudaGetSymbolAddress((void**)&a, g_a);
    cudaGetSymbolAddress((void**)&res, g_res);
    cudaGetSymbolAddress((void**)&x, g_x);
    cudaGetSymbolAddress((void**)&h, g_h);

    const int n_qd = Mrow * Dm;
    add_kernel<<<(n_qd + 255) / 256, 256>>>(src, pos, q, n_qd);

    // projections
    sgemm_nt<0><<<dim3(256 / 64, Mrow / 64), 256>>>(q, w_off, b_off, nullptr, nullptr, off, Mrow, 256, Dm);
    sgemm_nt<0><<<dim3(128 / 64, Mrow / 64), 256>>>(q, w_attn, b_attn, nullptr, nullptr, logits, Mrow, 128, Dm);
    sgemm_nt<2><<<dim3(256 / 64, Mrow / 64), 256>>>(src, w_value, b_value, nullptr, pad, value, Mrow, 256, Dm);

    // deformable attention core
    msdeform_kernel<<<Mrow, 256>>>(value, logits, off, ref, a);

    // output projection + residual, LN1
    sgemm_nt<3><<<dim3(Dm / 64, Mrow / 64), 256>>>(a, w_out, b_out, src, nullptr, res, Mrow, Dm, Dm);
    ln_kernel<<<Mrow / 8, 256>>>(res, g1, be1, x);

    // FFN
    sgemm_nt<1><<<dim3(FFm / 64, Mrow / 64), 256>>>(x, w1, b1, nullptr, nullptr, h, Mrow, FFm, Dm);
    sgemm_nt<3><<<dim3(Dm / 64, Mrow / 64), 256>>>(h, w2, b2, x, nullptr, res, Mrow, Dm, FFm);
    ln_kernel<<<Mrow / 8, 256>>>(res, g2, be2, out);
}

// round 7
// speedup vs baseline: 2.9908x; 2.9908x over previous
#include <cuda_runtime.h>
#include <cuda_bf16.h>
#include <math.h>

// Problem constants (fixed by the reference setup)
#define Bz   4
#define NTOK 5440            // 64*64 + 32*32 + 16*16 + 8*8
#define Dm   256
#define FFm  1024
#define NHh  8
#define NLl  4
#define NPp  4
#define DHd  32
#define Mrow (Bz * NTOK)     // 21760

// ---------------------------------------------------------------------------
// Scratch (device globals; no allocations allowed)
// ---------------------------------------------------------------------------
__device__ float g_q[Mrow * Dm];        // src + pos
__device__ float g_value[Mrow * Dm];    // value projection (masked)
__device__ float g_off[Mrow * 256];     // sampling offsets (NH*NL*NP*2 = 256)
__device__ float g_logits[Mrow * 128];  // attention logits (NH*NL*NP = 128)
__device__ float g_a[Mrow * Dm];        // msdeform output
__device__ float g_res[Mrow * Dm];      // pre-LN residual buffer (reused)
__device__ float g_x[Mrow * Dm];        // after LN1
__device__ float g_h[Mrow * FFm];       // FFN hidden

// ---------------------------------------------------------------------------
// Elementwise: q = src + pos
// ---------------------------------------------------------------------------
__global__ void add_kernel(const float* __restrict__ a, const float* __restrict__ b,
                           float* __restrict__ c, int n) {
    int i = blockIdx.x * blockDim.x + threadIdx.x;
    if (i < n) c[i] = a[i] + b[i];
}

// ---------------------------------------------------------------------------
// SGEMM (NT): C[M,N] = A[M,K] @ W[N,K]^T + bias, fused epilogues.
// BM=BN=128, BK=16, 256 threads, 8x8 microtile, float4 loads + reg prefetch.
// Transposed smem staging with STRIDE=132 padding (max 2-way STS conflict).
// Requires M%128==0, N%128==0, K%16==0.
// EPI: 0=plain  1=relu  2=zero-where-mask  3=add residual R[M,N]
// ---------------------------------------------------------------------------
template <int EPI>
__global__ __launch_bounds__(256, 2)
void sgemm_nt(const float* __restrict__ A, const float* __restrict__ W,
              const float* __restrict__ bias, const float* __restrict__ R,
              const unsigned char* __restrict__ mask,
              float* __restrict__ C, int M, int N, int K) {
    constexpr int BM = 128, BN = 128, BK = 16, STRIDE = 132;
    __shared__ float As[BK * STRIDE];
    __shared__ float Ws[BK * STRIDE];

    const int bm = blockIdx.y * BM;
    const int bn = blockIdx.x * BN;
    const int tid = threadIdx.x;
    const int tx = tid & 15;        // 0..15 -> 8 cols each
    const int ty = tid >> 4;        // 0..15 -> 8 rows each

    // Load mapping: tile = 128 rows x 16 k = 512 float4; thread does 2 float4
    // per operand (rows lrow0 and lrow0+64).
    const int lrow0 = tid >> 2;         // 0..63
    const int lkc   = (tid & 3) * 4;    // 0,4,8,12

    const float* Aptr = A + (size_t)(bm + lrow0) * K + lkc;
    const float* Wptr = W + (size_t)(bn + lrow0) * K + lkc;
    const size_t rowskip = (size_t)64 * K;

    float4 av0 = *(const float4*)(Aptr);
    float4 av1 = *(const float4*)(Aptr + rowskip);
    float4 wv0 = *(const float4*)(Wptr);
    float4 wv1 = *(const float4*)(Wptr + rowskip);

    float acc[8][8];
#pragma unroll
    for (int i = 0; i < 8; i++)
#pragma unroll
        for (int j = 0; j < 8; j++) acc[i][j] = 0.f;

    for (int k0 = 0; k0 < K; k0 += BK) {
        // stage registers -> smem (transposed)
        {
            const int r0 = lrow0, r1 = lrow0 + 64;
            As[(lkc + 0) * STRIDE + r0] = av0.x;
            As[(lkc + 1) * STRIDE + r0] = av0.y;
            As[(lkc + 2) * STRIDE + r0] = av0.z;
            As[(lkc + 3) * STRIDE + r0] = av0.w;
            As[(lkc + 0) * STRIDE + r1] = av1.x;
            As[(lkc + 1) * STRIDE + r1] = av1.y;
            As[(lkc + 2) * STRIDE + r1] = av1.z;
            As[(lkc + 3) * STRIDE + r1] = av1.w;
            Ws[(lkc + 0) * STRIDE + r0] = wv0.x;
            Ws[(lkc + 1) * STRIDE + r0] = wv0.y;
            Ws[(lkc + 2) * STRIDE + r0] = wv0.z;
            Ws[(lkc + 3) * STRIDE + r0] = wv0.w;
            Ws[(lkc + 0) * STRIDE + r1] = wv1.x;
            Ws[(lkc + 1) * STRIDE + r1] = wv1.y;
            Ws[(lkc + 2) * STRIDE + r1] = wv1.z;
            Ws[(lkc + 3) * STRIDE + r1] = wv1.w;
        }
        __syncthreads();

        // prefetch next k-tile into registers (overlaps with compute)
        if (k0 + BK < K) {
            const float* An = Aptr + k0 + BK;
            const float* Wn = Wptr + k0 + BK;
            av0 = *(const float4*)(An);
            av1 = *(const float4*)(An + rowskip);
            wv0 = *(const float4*)(Wn);
            wv1 = *(const float4*)(Wn + rowskip);
        }

#pragma unroll
        for (int kk = 0; kk < BK; kk++) {
            float a[8], w[8];
            *(float4*)&a[0] = *(const float4*)&As[kk * STRIDE + ty * 8];
            *(float4*)&a[4] = *(const float4*)&As[kk * STRIDE + ty * 8 + 4];
            *(float4*)&w[0] = *(const float4*)&Ws[kk * STRIDE + tx * 8];
            *(float4*)&w[4] = *(const float4*)&Ws[kk * STRIDE + tx * 8 + 4];
#pragma unroll
            for (int i = 0; i < 8; i++)
#pragma unroll
                for (int j = 0; j < 8; j++) acc[i][j] += a[i] * w[j];
        }
        __syncthreads();
    }

    // epilogue: bias + EPI, vectorized stores
#pragma unroll
    for (int i = 0; i < 8; i++) {
        const int row = bm + ty * 8 + i;
        const int col0 = bn + tx * 8;
        float v[8];
#pragma unroll
        for (int j = 0; j < 8; j++) {
            v[j] = acc[i][j] + bias[col0 + j];
            if (EPI == 1) v[j] = fmaxf(v[j], 0.f);
        }
        if (EPI == 2) {
            if (mask[row]) {
#pragma unroll
                for (int j = 0; j < 8; j++) v[j] = 0.f;
            }
        }
        if (EPI == 3) {
            float4 r0 = *(const float4*)&R[(size_t)row * N + col0];
            float4 r1 = *(const float4*)&R[(size_t)row * N + col0 + 4];
            v[0] += r0.x; v[1] += r0.y; v[2] += r0.z; v[3] += r0.w;
            v[4] += r1.x; v[5] += r1.y; v[6] += r1.z; v[7] += r1.w;
        }
        *(float4*)&C[(size_t)row * N + col0]     = make_float4(v[0], v[1], v[2], v[3]);
        *(float4*)&C[(size_t)row * N + col0 + 4] = make_float4(v[4], v[5], v[6], v[7]);
    }
}

// ---------------------------------------------------------------------------
// Multi-scale deformable attention core.
// Grid: Mrow blocks (one per (b, query)). Block: 256 threads = 8 warps,
// warp h handles head h; lane = channel d (DH=32). Softmax over the 16
// (level, point) samples is computed in-warp (lanes 0..15 carry s = lane&15).
// ---------------------------------------------------------------------------
__global__ __launch_bounds__(256)
void msdeform_kernel(const float* __restrict__ value,
                     const float* __restrict__ logits,
                     const float* __restrict__ off,
                     const float* __restrict__ ref,
                     float* __restrict__ out) {
    const int row = blockIdx.x;          // b * NTOK + q
    const int h = threadIdx.x >> 5;
    const int lane = threadIdx.x & 31;
    const int b = row / NTOK;
    const int s = lane & 15;

    // softmax over 16 samples of this head (replicated in both warp halves)
    float logit = logits[(size_t)row * 128 + h * 16 + s];
    float mx = logit;
#pragma unroll
    for (int o = 8; o; o >>= 1) mx = fmaxf(mx, __shfl_xor_sync(0xffffffffu, mx, o));
    float e = expf(logit - mx);
    float sm = e;
#pragma unroll
    for (int o = 8; o; o >>= 1) sm += __shfl_xor_sync(0xffffffffu, sm, o);
    float wn = e / sm;

    // this lane's sample offsets (sample index = s)
    float ox = off[(size_t)row * 256 + (h * 16 + s) * 2 + 0];
    float oy = off[(size_t)row * 256 + (h * 16 + s) * 2 + 1];

    const int   HWs[4]    = {64, 32, 16, 8};
    const int   starts[4] = {0, 4096, 5120, 5376};

    float acc = 0.f;
#pragma unroll
    for (int s2 = 0; s2 < 16; s2++) {
        const int l = s2 >> 2;
        const int HW = HWs[l];
        const float aw = __shfl_sync(0xffffffffu, wn, s2);
        const float sx = __shfl_sync(0xffffffffu, ox, s2);
        const float sy = __shfl_sync(0xffffffffu, oy, s2);

        const float rx = ref[((size_t)row * NLl + l) * 2 + 0];
        const float ry = ref[((size_t)row * NLl + l) * 2 + 1];
        const float invHW = 1.0f / (float)HW;

        // loc = ref + off/normalizer ; pixel = loc*W - 0.5
        const float px = (rx + sx * invHW) * (float)HW - 0.5f;
        const float py = (ry + sy * invHW) * (float)HW - 0.5f;
        const float x0f = floorf(px), y0f = floorf(py);
        const float fx = px - x0f, fy = py - y0f;
        const int x0 = (int)x0f, y0 = (int)y0f;

        float samp = 0.f;
#pragma unroll
        for (int c = 0; c < 4; c++) {
            const int xi = x0 + (c & 1);
            const int yi = y0 + (c >> 1);
            const float w = ((c & 1) ? fx : 1.f - fx) * ((c >> 1) ? fy : 1.f - fy);
            if (xi >= 0 && xi < HW && yi >= 0 && yi < HW) {
                const size_t vrow = (size_t)b * NTOK + starts[l] + yi * HW + xi;
                samp += w * value[(vrow * NHh + h) * DHd + lane];
            }
        }
        acc += aw * samp;
    }
    out[(size_t)row * Dm + h * DHd + lane] = acc;
}

// ---------------------------------------------------------------------------
// LayerNorm over last dim (256). One warp per row, 8 rows per block.
// Input X already contains the residual sum.
// ---------------------------------------------------------------------------
__global__ __launch_bounds__(256)
void ln_kernel(const float* __restrict__ X, const float* __restrict__ g,
               const float* __restrict__ be, float* __restrict__ Y) {
    const int row = blockIdx.x * 8 + (threadIdx.x >> 5);
    const int lane = threadIdx.x & 31;
    const float* x = X + (size_t)row * Dm;

    float v[8];
    float s = 0.f, ss = 0.f;
#pragma unroll
    for (int j = 0; j < 8; j++) {
        v[j] = x[lane + 32 * j];
        s += v[j];
        ss += v[j] * v[j];
    }
#pragma unroll
    for (int o = 16; o; o >>= 1) {
        s  += __shfl_xor_sync(0xffffffffu, s, o);
        ss += __shfl_xor_sync(0xffffffffu, ss, o);
    }
    const float mean = s * (1.0f / 256.0f);
    const float var  = ss * (1.0f / 256.0f) - mean * mean;
    const float rs   = rsqrtf(var + 1e-5f);
#pragma unroll
    for (int j = 0; j < 8; j++) {
        const int c = lane + 32 * j;
        Y[(size_t)row * Dm + c] = (v[j] - mean) * rs * g[c] + be[c];
    }
}

// ---------------------------------------------------------------------------
// Launch
// ---------------------------------------------------------------------------
extern "C" void kernel_launch(void* const* d_in, const int* in_sizes, int n_in,
                              void* d_out, int out_size) {
    const float* src  = (const float*)d_in[0];
    const float* pos  = (const float*)d_in[1];
    const float* ref  = (const float*)d_in[2];
    const float* w_value = (const float*)d_in[3];
    const float* b_value = (const float*)d_in[4];
    const float* w_off   = (const float*)d_in[5];
    const float* b_off   = (const float*)d_in[6];
    const float* w_attn  = (const float*)d_in[7];
    const float* b_attn  = (const float*)d_in[8];
    const float* w_out   = (const float*)d_in[9];
    const float* b_out   = (const float*)d_in[10];
    const float* g1  = (const float*)d_in[11];
    const float* be1 = (const float*)d_in[12];
    const float* w1  = (const float*)d_in[13];
    const float* b1  = (const float*)d_in[14];
    const float* w2  = (const float*)d_in[15];
    const float* b2  = (const float*)d_in[16];
    const float* g2  = (const float*)d_in[17];
    const float* be2 = (const float*)d_in[18];
    // d_in[19] spatial_shapes, d_in[20] level_start_index: fixed, hardcoded
    const unsigned char* pad = (const unsigned char*)d_in[21];

    float* out = (float*)d_out;

    float *q, *value, *off, *logits, *a, *res, *x, *h;
    cudaGetSymbolAddress((void**)&q, g_q);
    cudaGetSymbolAddress((void**)&value, g_value);
    cudaGetSymbolAddress((void**)&off, g_off);
    cudaGetSymbolAddress((void**)&logits, g_logits);
    cudaGetSymbolAddress((void**)&a, g_a);
    cudaGetSymbolAddress((void**)&res, g_res);
    cudaGetSymbolAddress((void**)&x, g_x);
    cudaGetSymbolAddress((void**)&h, g_h);

    const int n_qd = Mrow * Dm;
    add_kernel<<<(n_qd + 255) / 256, 256>>>(src, pos, q, n_qd);

    // projections (grid: N/128 x M/128)
    sgemm_nt<0><<<dim3(256 / 128, Mrow / 128), 256>>>(q, w_off, b_off, nullptr, nullptr, off, Mrow, 256, Dm);
    sgemm_nt<0><<<dim3(128 / 128, Mrow / 128), 256>>>(q, w_attn, b_attn, nullptr, nullptr, logits, Mrow, 128, Dm);
    sgemm_nt<2><<<dim3(256 / 128, Mrow / 128), 256>>>(src, w_value, b_value, nullptr, pad, value, Mrow, 256, Dm);

    // deformable attention core
    msdeform_kernel<<<Mrow, 256>>>(value, logits, off, ref, a);

    // output projection + residual, LN1
    sgemm_nt<3><<<dim3(Dm / 128, Mrow / 128), 256>>>(a, w_out, b_out, src, nullptr, res, Mrow, Dm, Dm);
    ln_kernel<<<Mrow / 8, 256>>>(res, g1, be1, x);

    // FFN
    sgemm_nt<1><<<dim3(FFm / 128, Mrow / 128), 256>>>(x, w1, b1, nullptr, nullptr, h, Mrow, FFm, Dm);
    sgemm_nt<3><<<dim3(Dm / 128, Mrow / 128), 256>>>(h, w2, b2, x, nullptr, res, Mrow, Dm, FFm);
    ln_kernel<<<Mrow / 8, 256>>>(res, g2, be2, out);
}

// round 8
// speedup vs baseline: 5.3700x; 1.7955x over previous
#include <cuda_runtime.h>
#include <cuda_bf16.h>
#include <math.h>
#include <stdint.h>

// Problem constants (fixed by the reference setup)
#define Bz   4
#define NTOK 5440            // 64*64 + 32*32 + 16*16 + 8*8
#define Dm   256
#define FFm  1024
#define NHh  8
#define NLl  4
#define NPp  4
#define DHd  32
#define Mrow (Bz * NTOK)     // 21760

// ---------------------------------------------------------------------------
// Scratch (device globals; no allocations allowed)
// ---------------------------------------------------------------------------
__device__ float g_q[Mrow * Dm];        // src + pos
__device__ float g_value[Mrow * Dm];    // value projection (masked)
__device__ float g_off[Mrow * 256];     // sampling offsets (NH*NL*NP*2 = 256)
__device__ float g_logits[Mrow * 128];  // attention logits (NH*NL*NP = 128)
__device__ float g_a[Mrow * Dm];        // msdeform output
__device__ float g_res[Mrow * Dm];      // pre-LN residual buffer (reused)
__device__ float g_x[Mrow * Dm];        // after LN1
__device__ float g_h[Mrow * FFm];       // FFN hidden

// ---------------------------------------------------------------------------
// Helpers
// ---------------------------------------------------------------------------
__device__ __forceinline__ uint32_t smem_u32(const void* p) {
    return (uint32_t)__cvta_generic_to_shared(p);
}
__device__ __forceinline__ uint32_t f2tf32(float f) {
    uint32_t r;
    asm("cvt.rna.tf32.f32 %0, %1;" : "=r"(r) : "f"(f));
    return r;
}
__device__ __forceinline__ void mma_tf32(float c[4], const uint32_t a[4], const uint32_t b[2]) {
    asm volatile(
        "mma.sync.aligned.m16n8k8.row.col.f32.tf32.tf32.f32 "
        "{%0,%1,%2,%3}, {%4,%5,%6,%7}, {%8,%9}, {%0,%1,%2,%3};"
        : "+f"(c[0]), "+f"(c[1]), "+f"(c[2]), "+f"(c[3])
        : "r"(a[0]), "r"(a[1]), "r"(a[2]), "r"(a[3]), "r"(b[0]), "r"(b[1]));
}

// ---------------------------------------------------------------------------
// Elementwise: q = src + pos
// ---------------------------------------------------------------------------
__global__ void add_kernel(const float* __restrict__ a, const float* __restrict__ b,
                           float* __restrict__ c, int n) {
    int i = blockIdx.x * blockDim.x + threadIdx.x;
    if (i < n) c[i] = a[i] + b[i];
}

// ---------------------------------------------------------------------------
// Tensor-core GEMM (NT): C[M,N] = A[M,K] @ W[N,K]^T + bias, fused epilogues.
// tf32 mma.sync m16n8k8, fp32 accumulate. Swapped operands:
//   mma-M dim = W rows (n), mma-N dim = A rows (m).
// Block: 128 (m) x 128 (n) x BK=16. 256 threads = 8 warps, warp tile
// 64(n) x 32(m). W staged in smem [n][pitch 20] (ldmatrix, conflict-free);
// A staged transposed [k][pitch 132] (scalar LDS B-fragments).
// Requires M%128==0, N%128==0, K%16==0.
// EPI: 0=plain  1=relu  2=zero-where-mask  3=add residual R[M,N]
// ---------------------------------------------------------------------------
template <int EPI>
__global__ __launch_bounds__(256, 2)
void tmma_nt(const float* __restrict__ A, const float* __restrict__ W,
             const float* __restrict__ bias, const float* __restrict__ R,
             const unsigned char* __restrict__ mask,
             float* __restrict__ C, int M, int N, int K) {
    constexpr int BM = 128, BN = 128, BK = 16;
    constexpr int XPITCH = 132;   // A (activation) staging: [BK][XPITCH]
    constexpr int WPITCH = 20;    // W staging: [BN][WPITCH] (80 B rows, 16B-aligned)
    __shared__ float Xs[BK * XPITCH];
    __shared__ float Ws[BN * WPITCH];

    const int bm = blockIdx.y * BM;
    const int bn = blockIdx.x * BN;
    const int tid = threadIdx.x;
    const int warp = tid >> 5;
    const int lane = tid & 31;
    const int warp_w = warp >> 2;   // 0..1 -> n-offset 64*warp_w
    const int warp_x = warp & 3;    // 0..3 -> m-offset 32*warp_x

    // global->reg staging mapping: thread loads rows lrow0 and lrow0+64,
    // 4 consecutive k at lkc.
    const int lrow0 = tid >> 2;         // 0..63
    const int lkc   = (tid & 3) * 4;    // 0,4,8,12

    const float* Aptr = A + (size_t)(bm + lrow0) * K + lkc;
    const float* Wptr = W + (size_t)(bn + lrow0) * K + lkc;
    const size_t rowskip = (size_t)64 * K;

    float4 av0 = *(const float4*)(Aptr);
    float4 av1 = *(const float4*)(Aptr + rowskip);
    float4 wv0 = *(const float4*)(Wptr);
    float4 wv1 = *(const float4*)(Wptr + rowskip);

    float acc[4][4][4];
#pragma unroll
    for (int i = 0; i < 4; i++)
#pragma unroll
        for (int j = 0; j < 4; j++)
#pragma unroll
            for (int c = 0; c < 4; c++) acc[i][j][c] = 0.f;

    // ldmatrix per-lane row addressing: quad q selects which 8x8 b16 matrix.
    const int q = lane >> 3;
    const int ldm_row  = warp_w * 64 + (q & 1) * 8 + (lane & 7);
    const int ldm_koff = (q >> 1) * 4;
    const uint32_t ws_u32 = smem_u32(Ws);

    for (int k0 = 0; k0 < K; k0 += BK) {
        // stage A transposed [k][m]
        {
            const int r0 = lrow0, r1 = lrow0 + 64;
            Xs[(lkc + 0) * XPITCH + r0] = av0.x;
            Xs[(lkc + 1) * XPITCH + r0] = av0.y;
            Xs[(lkc + 2) * XPITCH + r0] = av0.z;
            Xs[(lkc + 3) * XPITCH + r0] = av0.w;
            Xs[(lkc + 0) * XPITCH + r1] = av1.x;
            Xs[(lkc + 1) * XPITCH + r1] = av1.y;
            Xs[(lkc + 2) * XPITCH + r1] = av1.z;
            Xs[(lkc + 3) * XPITCH + r1] = av1.w;
            // stage W row-major [n][k] (float4, 16B-aligned since WPITCH*4=80)
            *(float4*)&Ws[(size_t)lrow0 * WPITCH + lkc]        = wv0;
            *(float4*)&Ws[(size_t)(lrow0 + 64) * WPITCH + lkc] = wv1;
        }
        __syncthreads();

        if (k0 + BK < K) {
            const float* An = Aptr + k0 + BK;
            const float* Wn = Wptr + k0 + BK;
            av0 = *(const float4*)(An);
            av1 = *(const float4*)(An + rowskip);
            wv0 = *(const float4*)(Wn);
            wv1 = *(const float4*)(Wn + rowskip);
        }

#pragma unroll
        for (int k8 = 0; k8 < BK; k8 += 8) {
            // A-operand fragments (W tile) via ldmatrix
            uint32_t a[4][4];
#pragma unroll
            for (int i = 0; i < 4; i++) {
                uint32_t addr = ws_u32 +
                    (uint32_t)(((ldm_row + i * 16) * WPITCH + k8 + ldm_koff) * 4);
                asm volatile(
                    "ldmatrix.sync.aligned.m8n8.x4.shared.b16 {%0,%1,%2,%3}, [%4];"
                    : "=r"(a[i][0]), "=r"(a[i][1]), "=r"(a[i][2]), "=r"(a[i][3])
                    : "r"(addr));
            }
#pragma unroll
            for (int i = 0; i < 4; i++)
#pragma unroll
                for (int r = 0; r < 4; r++)
                    a[i][r] = f2tf32(__uint_as_float(a[i][r]));

            // B-operand fragments (activation tile) via scalar LDS
            uint32_t b[4][2];
            const int bk  = (k8 + (lane & 3)) * XPITCH;
            const int bm0 = warp_x * 32 + (lane >> 2);
#pragma unroll
            for (int j = 0; j < 4; j++) {
                b[j][0] = f2tf32(Xs[bk + bm0 + j * 8]);
                b[j][1] = f2tf32(Xs[bk + 4 * XPITCH + bm0 + j * 8]);
            }

#pragma unroll
            for (int i = 0; i < 4; i++)
#pragma unroll
                for (int j = 0; j < 4; j++)
                    mma_tf32(acc[i][j], a[i], b[j]);
        }
        __syncthreads();
    }

    // epilogue: C[m][n] = acc + bias[n] (+EPI). c-frag: c0:(r,2t) c1:(r,2t+1)
    // c2:(r+8,2t) c3:(r+8,2t+1) in (n,m)-space.
    const int r4 = lane >> 2;
    const int t4 = lane & 3;
#pragma unroll
    for (int i = 0; i < 4; i++) {
        const int n0g = bn + warp_w * 64 + i * 16 + r4;
        const float bi0 = bias[n0g];
        const float bi1 = bias[n0g + 8];
#pragma unroll
        for (int j = 0; j < 4; j++) {
            const int mb = bm + warp_x * 32 + j * 8 + t4 * 2;
#pragma unroll
            for (int cr = 0; cr < 4; cr++) {
                const int n = n0g + (cr >> 1) * 8;
                const int m = mb + (cr & 1);
                float v = acc[i][j][cr] + ((cr >> 1) ? bi1 : bi0);
                if (EPI == 1) v = fmaxf(v, 0.f);
                if (EPI == 2) { if (mask[m]) v = 0.f; }
                if (EPI == 3) v += R[(size_t)m * N + n];
                C[(size_t)m * N + n] = v;
            }
        }
    }
}

// ---------------------------------------------------------------------------
// Multi-scale deformable attention core.
// ---------------------------------------------------------------------------
__global__ __launch_bounds__(256)
void msdeform_kernel(const float* __restrict__ value,
                     const float* __restrict__ logits,
                     const float* __restrict__ off,
                     const float* __restrict__ ref,
                     float* __restrict__ out) {
    const int row = blockIdx.x;          // b * NTOK + q
    const int h = threadIdx.x >> 5;
    const int lane = threadIdx.x & 31;
    const int b = row / NTOK;
    const int s = lane & 15;

    // softmax over 16 samples of this head (replicated in both warp halves)
    float logit = logits[(size_t)row * 128 + h * 16 + s];
    float mx = logit;
#pragma unroll
    for (int o = 8; o; o >>= 1) mx = fmaxf(mx, __shfl_xor_sync(0xffffffffu, mx, o));
    float e = expf(logit - mx);
    float sm = e;
#pragma unroll
    for (int o = 8; o; o >>= 1) sm += __shfl_xor_sync(0xffffffffu, sm, o);
    float wn = e / sm;

    // this lane's sample offsets (sample index = s)
    float ox = off[(size_t)row * 256 + (h * 16 + s) * 2 + 0];
    float oy = off[(size_t)row * 256 + (h * 16 + s) * 2 + 1];

    const int   HWs[4]    = {64, 32, 16, 8};
    const int   starts[4] = {0, 4096, 5120, 5376};

    float acc = 0.f;
#pragma unroll
    for (int s2 = 0; s2 < 16; s2++) {
        const int l = s2 >> 2;
        const int HW = HWs[l];
        const float aw = __shfl_sync(0xffffffffu, wn, s2);
        const float sx = __shfl_sync(0xffffffffu, ox, s2);
        const float sy = __shfl_sync(0xffffffffu, oy, s2);

        const float rx = ref[((size_t)row * NLl + l) * 2 + 0];
        const float ry = ref[((size_t)row * NLl + l) * 2 + 1];
        const float invHW = 1.0f / (float)HW;

        // loc = ref + off/normalizer ; pixel = loc*W - 0.5
        const float px = (rx + sx * invHW) * (float)HW - 0.5f;
        const float py = (ry + sy * invHW) * (float)HW - 0.5f;
        const float x0f = floorf(px), y0f = floorf(py);
        const float fx = px - x0f, fy = py - y0f;
        const int x0 = (int)x0f, y0 = (int)y0f;

        float samp = 0.f;
#pragma unroll
        for (int c = 0; c < 4; c++) {
            const int xi = x0 + (c & 1);
            const int yi = y0 + (c >> 1);
            const float w = ((c & 1) ? fx : 1.f - fx) * ((c >> 1) ? fy : 1.f - fy);
            if (xi >= 0 && xi < HW && yi >= 0 && yi < HW) {
                const size_t vrow = (size_t)b * NTOK + starts[l] + yi * HW + xi;
                samp += w * value[(vrow * NHh + h) * DHd + lane];
            }
        }
        acc += aw * samp;
    }
    out[(size_t)row * Dm + h * DHd + lane] = acc;
}

// ---------------------------------------------------------------------------
// LayerNorm over last dim (256). One warp per row, 8 rows per block.
// ---------------------------------------------------------------------------
__global__ __launch_bounds__(256)
void ln_kernel(const float* __restrict__ X, const float* __restrict__ g,
               const float* __restrict__ be, float* __restrict__ Y) {
    const int row = blockIdx.x * 8 + (threadIdx.x >> 5);
    const int lane = threadIdx.x & 31;
    const float* x = X + (size_t)row * Dm;

    float v[8];
    float s = 0.f, ss = 0.f;
#pragma unroll
    for (int j = 0; j < 8; j++) {
        v[j] = x[lane + 32 * j];
        s += v[j];
        ss += v[j] * v[j];
    }
#pragma unroll
    for (int o = 16; o; o >>= 1) {
        s  += __shfl_xor_sync(0xffffffffu, s, o);
        ss += __shfl_xor_sync(0xffffffffu, ss, o);
    }
    const float mean = s * (1.0f / 256.0f);
    const float var  = ss * (1.0f / 256.0f) - mean * mean;
    const float rs   = rsqrtf(var + 1e-5f);
#pragma unroll
    for (int j = 0; j < 8; j++) {
        const int c = lane + 32 * j;
        Y[(size_t)row * Dm + c] = (v[j] - mean) * rs * g[c] + be[c];
    }
}

// ---------------------------------------------------------------------------
// Launch
// ---------------------------------------------------------------------------
extern "C" void kernel_launch(void* const* d_in, const int* in_sizes, int n_in,
                              void* d_out, int out_size) {
    const float* src  = (const float*)d_in[0];
    const float* pos  = (const float*)d_in[1];
    const float* ref  = (const float*)d_in[2];
    const float* w_value = (const float*)d_in[3];
    const float* b_value = (const float*)d_in[4];
    const float* w_off   = (const float*)d_in[5];
    const float* b_off   = (const float*)d_in[6];
    const float* w_attn  = (const float*)d_in[7];
    const float* b_attn  = (const float*)d_in[8];
    const float* w_out   = (const float*)d_in[9];
    const float* b_out   = (const float*)d_in[10];
    const float* g1  = (const float*)d_in[11];
    const float* be1 = (const float*)d_in[12];
    const float* w1  = (const float*)d_in[13];
    const float* b1  = (const float*)d_in[14];
    const float* w2  = (const float*)d_in[15];
    const float* b2  = (const float*)d_in[16];
    const float* g2  = (const float*)d_in[17];
    const float* be2 = (const float*)d_in[18];
    // d_in[19] spatial_shapes, d_in[20] level_start_index: fixed, hardcoded
    const unsigned char* pad = (const unsigned char*)d_in[21];

    float* out = (float*)d_out;

    float *q, *value, *off, *logits, *a, *res, *x, *h;
    cudaGetSymbolAddress((void**)&q, g_q);
    cudaGetSymbolAddress((void**)&value, g_value);
    cudaGetSymbolAddress((void**)&off, g_off);
    cudaGetSymbolAddress((void**)&logits, g_logits);
    cudaGetSymbolAddress((void**)&a, g_a);
    cudaGetSymbolAddress((void**)&res, g_res);
    cudaGetSymbolAddress((void**)&x, g_x);
    cudaGetSymbolAddress((void**)&h, g_h);

    const int n_qd = Mrow * Dm;
    add_kernel<<<(n_qd + 255) / 256, 256>>>(src, pos, q, n_qd);

    // projections (grid: N/128 x M/128)
    tmma_nt<0><<<dim3(256 / 128, Mrow / 128), 256>>>(q, w_off, b_off, nullptr, nullptr, off, Mrow, 256, Dm);
    tmma_nt<0><<<dim3(128 / 128, Mrow / 128), 256>>>(q, w_attn, b_attn, nullptr, nullptr, logits, Mrow, 128, Dm);
    tmma_nt<2><<<dim3(256 / 128, Mrow / 128), 256>>>(src, w_value, b_value, nullptr, pad, value, Mrow, 256, Dm);

    // deformable attention core
    msdeform_kernel<<<Mrow, 256>>>(value, logits, off, ref, a);

    // output projection + residual, LN1
    tmma_nt<3><<<dim3(Dm / 128, Mrow / 128), 256>>>(a, w_out, b_out, src, nullptr, res, Mrow, Dm, Dm);
    ln_kernel<<<Mrow / 8, 256>>>(res, g1, be1, x);

    // FFN
    tmma_nt<1><<<dim3(FFm / 128, Mrow / 128), 256>>>(x, w1, b1, nullptr, nullptr, h, Mrow, FFm, Dm);
    tmma_nt<3><<<dim3(Dm / 128, Mrow / 128), 256>>>(h, w2, b2, x, nullptr, res, Mrow, Dm, FFm);
    ln_kernel<<<Mrow / 8, 256>>>(res, g2, be2, out);
}

// round 10
// speedup vs baseline: 5.6688x; 1.0556x over previous
#include <cuda_runtime.h>
#include <cuda_bf16.h>
#include <math.h>
#include <stdint.h>

// Problem constants (fixed by the reference setup)
#define Bz   4
#define NTOK 5440            // 64*64 + 32*32 + 16*16 + 8*8
#define Dm   256
#define FFm  1024
#define NHh  8
#define NLl  4
#define NPp  4
#define DHd  32
#define Mrow (Bz * NTOK)     // 21760

// ---------------------------------------------------------------------------
// Scratch (device globals; no allocations allowed)
// ---------------------------------------------------------------------------
__device__ float g_value[Mrow * Dm];    // value projection (masked)
__device__ float g_off[Mrow * 256];     // sampling offsets (NH*NL*NP*2 = 256)
__device__ float g_logits[Mrow * 128];  // attention logits (NH*NL*NP = 128)
__device__ float g_a[Mrow * Dm];        // msdeform output
__device__ float g_res[Mrow * Dm];      // pre-LN residual buffer (reused)
__device__ float g_x[Mrow * Dm];        // after LN1
__device__ float g_h[Mrow * FFm];       // FFN hidden

// ---------------------------------------------------------------------------
// Helpers
// ---------------------------------------------------------------------------
__device__ __forceinline__ uint32_t smem_u32(const void* p) {
    return (uint32_t)__cvta_generic_to_shared(p);
}
__device__ __forceinline__ uint32_t f2tf32(float f) {
    uint32_t r;
    asm("cvt.rna.tf32.f32 %0, %1;" : "=r"(r) : "f"(f));
    return r;
}
__device__ __forceinline__ float4 cvt4(float4 v) {
    float4 r;
    r.x = __uint_as_float(f2tf32(v.x));
    r.y = __uint_as_float(f2tf32(v.y));
    r.z = __uint_as_float(f2tf32(v.z));
    r.w = __uint_as_float(f2tf32(v.w));
    return r;
}
__device__ __forceinline__ void mma_tf32(float c[4], const uint32_t a[4], const uint32_t b[2]) {
    asm volatile(
        "mma.sync.aligned.m16n8k8.row.col.f32.tf32.tf32.f32 "
        "{%0,%1,%2,%3}, {%4,%5,%6,%7}, {%8,%9}, {%0,%1,%2,%3};"
        : "+f"(c[0]), "+f"(c[1]), "+f"(c[2]), "+f"(c[3])
        : "r"(a[0]), "r"(a[1]), "r"(a[2]), "r"(a[3]), "r"(b[0]), "r"(b[1]));
}

// ---------------------------------------------------------------------------
// Tensor-core GEMM (NT): C[M,N] = A[M,K] @ W[N,K]^T + bias, fused epilogues.
// tf32 mma.sync m16n8k8, fp32 accumulate. Swapped operands (mma-M = W rows).
// Block 128(m) x 128(n) x BK=16, 8 warps, warp tile 64(n) x 32(m).
// BOTH operands staged row-major [row][k] pitch-20 as pre-converted tf32
// bits; A- and B-fragments both fetched via ldmatrix (conflict-free rows).
// ADDPOS: stage A as A + A2 (fuses q = src + pos).
// EPI: 0=plain  1=relu  2=zero-where-mask  3=add residual R[M,N]
// ---------------------------------------------------------------------------
template <int EPI, int ADDPOS>
__global__ __launch_bounds__(256, 2)
void tmma_nt(const float* __restrict__ A, const float* __restrict__ A2,
             const float* __restrict__ W,
             const float* __restrict__ bias, const float* __restrict__ R,
             const unsigned char* __restrict__ mask,
             float* __restrict__ C, int M, int N, int K) {
    constexpr int BK = 16;
    constexpr int PITCH = 20;     // 80 B rows, 16B-aligned, ldmatrix conflict-free
    __shared__ float Xs[128 * PITCH];
    __shared__ float Ws[128 * PITCH];

    const int bm = blockIdx.y * 128;
    const int bn = blockIdx.x * 128;
    const int tid = threadIdx.x;
    const int warp = tid >> 5;
    const int lane = tid & 31;
    const int warp_w = warp >> 2;   // 0..1 -> n-offset 64*warp_w
    const int warp_x = warp & 3;    // 0..3 -> m-offset 32*warp_x

    // global->smem staging: thread loads rows lrow0, lrow0+64; 4 k at lkc.
    const int lrow0 = tid >> 2;         // 0..63
    const int lkc   = (tid & 3) * 4;    // 0,4,8,12

    const float* Aptr  = A + (size_t)(bm + lrow0) * K + lkc;
    const float* A2ptr = ADDPOS ? (A2 + (size_t)(bm + lrow0) * K + lkc) : A;
    const float* Wptr  = W + (size_t)(bn + lrow0) * K + lkc;
    const size_t rowskip = (size_t)64 * K;

    float4 av0 = *(const float4*)(Aptr);
    float4 av1 = *(const float4*)(Aptr + rowskip);
    float4 wv0 = *(const float4*)(Wptr);
    float4 wv1 = *(const float4*)(Wptr + rowskip);
    float4 pv0, pv1;
    if (ADDPOS) {
        pv0 = *(const float4*)(A2ptr);
        pv1 = *(const float4*)(A2ptr + rowskip);
    }

    float acc[4][4][4];
#pragma unroll
    for (int i = 0; i < 4; i++)
#pragma unroll
        for (int j = 0; j < 4; j++)
#pragma unroll
            for (int c = 0; c < 4; c++) acc[i][j][c] = 0.f;

    // A-fragment (W tile) ldmatrix addressing
    const int q = lane >> 3;
    const int ldm_row  = warp_w * 64 + (q & 1) * 8 + (lane & 7);
    const int ldm_koff = (q >> 1) * 4;
    const uint32_t ws_u32 = smem_u32(Ws);
    // B-fragment (X tile) ldmatrix addressing: matrices = (j-block, k-half)
    const int brow = warp_x * 32 + ((q >> 1) << 3) + (lane & 7);
    const int bcol = (q & 1) * 4;
    const uint32_t xs_u32 = smem_u32(Xs) + (uint32_t)((brow * PITCH + bcol) * 4);

    for (int k0 = 0; k0 < K; k0 += BK) {
        // stage both operands as tf32 bits, row-major [row][k]
        {
            float4 a0 = av0, a1 = av1;
            if (ADDPOS) {
                a0.x += pv0.x; a0.y += pv0.y; a0.z += pv0.z; a0.w += pv0.w;
                a1.x += pv1.x; a1.y += pv1.y; a1.z += pv1.z; a1.w += pv1.w;
            }
            *(float4*)&Xs[(size_t)lrow0 * PITCH + lkc]        = cvt4(a0);
            *(float4*)&Xs[(size_t)(lrow0 + 64) * PITCH + lkc] = cvt4(a1);
            *(float4*)&Ws[(size_t)lrow0 * PITCH + lkc]        = cvt4(wv0);
            *(float4*)&Ws[(size_t)(lrow0 + 64) * PITCH + lkc] = cvt4(wv1);
        }
        __syncthreads();

        if (k0 + BK < K) {
            const float* An = Aptr + k0 + BK;
            const float* Wn = Wptr + k0 + BK;
            av0 = *(const float4*)(An);
            av1 = *(const float4*)(An + rowskip);
            wv0 = *(const float4*)(Wn);
            wv1 = *(const float4*)(Wn + rowskip);
            if (ADDPOS) {
                const float* Pn = A2ptr + k0 + BK;
                pv0 = *(const float4*)(Pn);
                pv1 = *(const float4*)(Pn + rowskip);
            }
        }

#pragma unroll
        for (int k8 = 0; k8 < BK; k8 += 8) {
            // A-operand fragments (W tile)
            uint32_t a[4][4];
#pragma unroll
            for (int i = 0; i < 4; i++) {
                uint32_t addr = ws_u32 +
                    (uint32_t)(((ldm_row + i * 16) * PITCH + k8 + ldm_koff) * 4);
                asm volatile(
                    "ldmatrix.sync.aligned.m8n8.x4.shared.b16 {%0,%1,%2,%3}, [%4];"
                    : "=r"(a[i][0]), "=r"(a[i][1]), "=r"(a[i][2]), "=r"(a[i][3])
                    : "r"(addr));
            }
            // B-operand fragments (X tile): 2 x ldmatrix.x4 cover j=0..3
            uint32_t b[4][2];
            {
                uint32_t addr0 = xs_u32 + (uint32_t)(k8 * 4);
                uint32_t addr1 = addr0 + (uint32_t)(16 * PITCH * 4);
                asm volatile(
                    "ldmatrix.sync.aligned.m8n8.x4.shared.b16 {%0,%1,%2,%3}, [%4];"
                    : "=r"(b[0][0]), "=r"(b[0][1]), "=r"(b[1][0]), "=r"(b[1][1])
                    : "r"(addr0));
                asm volatile(
                    "ldmatrix.sync.aligned.m8n8.x4.shared.b16 {%0,%1,%2,%3}, [%4];"
                    : "=r"(b[2][0]), "=r"(b[2][1]), "=r"(b[3][0]), "=r"(b[3][1])
                    : "r"(addr1));
            }

#pragma unroll
            for (int i = 0; i < 4; i++)
#pragma unroll
                for (int j = 0; j < 4; j++)
                    mma_tf32(acc[i][j], a[i], b[j]);
        }
        __syncthreads();
    }

    // epilogue: C[m][n] = acc + bias[n] (+EPI). c-frag: c0:(r,2t) c1:(r,2t+1)
    // c2:(r+8,2t) c3:(r+8,2t+1) in (n,m)-space.
    const int r4 = lane >> 2;
    const int t4 = lane & 3;
#pragma unroll
    for (int i = 0; i < 4; i++) {
        const int n0g = bn + warp_w * 64 + i * 16 + r4;
        const float bi0 = bias[n0g];
        const float bi1 = bias[n0g + 8];
#pragma unroll
        for (int j = 0; j < 4; j++) {
            const int mb = bm + warp_x * 32 + j * 8 + t4 * 2;
#pragma unroll
            for (int cr = 0; cr < 4; cr++) {
                const int n = n0g + (cr >> 1) * 8;
                const int m = mb + (cr & 1);
                float v = acc[i][j][cr] + ((cr >> 1) ? bi1 : bi0);
                if (EPI == 1) v = fmaxf(v, 0.f);
                if (EPI == 2) { if (mask[m]) v = 0.f; }
                if (EPI == 3) v += R[(size_t)m * N + n];
                C[(size_t)m * N + n] = v;
            }
        }
    }
}

// ---------------------------------------------------------------------------
// Multi-scale deformable attention core.
// ---------------------------------------------------------------------------
__global__ __launch_bounds__(256)
void msdeform_kernel(const float* __restrict__ value,
                     const float* __restrict__ logits,
                     const float* __restrict__ off,
                     const float* __restrict__ ref,
                     float* __restrict__ out) {
    const int row = blockIdx.x;          // b * NTOK + q
    const int h = threadIdx.x >> 5;
    const int lane = threadIdx.x & 31;
    const int b = row / NTOK;
    const int s = lane & 15;

    // softmax over 16 samples of this head (replicated in both warp halves)
    float logit = logits[(size_t)row * 128 + h * 16 + s];
    float mx = logit;
#pragma unroll
    for (int o = 8; o; o >>= 1) mx = fmaxf(mx, __shfl_xor_sync(0xffffffffu, mx, o));
    float e = expf(logit - mx);
    float sm = e;
#pragma unroll
    for (int o = 8; o; o >>= 1) sm += __shfl_xor_sync(0xffffffffu, sm, o);
    float wn = e / sm;

    // this lane's sample offsets (sample index = s)
    float ox = off[(size_t)row * 256 + (h * 16 + s) * 2 + 0];
    float oy = off[(size_t)row * 256 + (h * 16 + s) * 2 + 1];

    const int   HWs[4]    = {64, 32, 16, 8};
    const int   starts[4] = {0, 4096, 5120, 5376};

    float acc = 0.f;
#pragma unroll
    for (int s2 = 0; s2 < 16; s2++) {
        const int l = s2 >> 2;
        const int HW = HWs[l];
        const float aw = __shfl_sync(0xffffffffu, wn, s2);
        const float sx = __shfl_sync(0xffffffffu, ox, s2);
        const float sy = __shfl_sync(0xffffffffu, oy, s2);

        const float rx = ref[((size_t)row * NLl + l) * 2 + 0];
        const float ry = ref[((size_t)row * NLl + l) * 2 + 1];
        const float invHW = 1.0f / (float)HW;

        // loc = ref + off/normalizer ; pixel = loc*W - 0.5
        const float px = (rx + sx * invHW) * (float)HW - 0.5f;
        const float py = (ry + sy * invHW) * (float)HW - 0.5f;
        const float x0f = floorf(px), y0f = floorf(py);
        const float fx = px - x0f, fy = py - y0f;
        const int x0 = (int)x0f, y0 = (int)y0f;

        float samp = 0.f;
#pragma unroll
        for (int c = 0; c < 4; c++) {
            const int xi = x0 + (c & 1);
            const int yi = y0 + (c >> 1);
            const float w = ((c & 1) ? fx : 1.f - fx) * ((c >> 1) ? fy : 1.f - fy);
            if (xi >= 0 && xi < HW && yi >= 0 && yi < HW) {
                const size_t vrow = (size_t)b * NTOK + starts[l] + yi * HW + xi;
                samp += w * value[(vrow * NHh + h) * DHd + lane];
            }
        }
        acc += aw * samp;
    }
    out[(size_t)row * Dm + h * DHd + lane] = acc;
}

// ---------------------------------------------------------------------------
// LayerNorm over last dim (256). One warp per row, 8 rows per block.
// ---------------------------------------------------------------------------
__global__ __launch_bounds__(256)
void ln_kernel(const float* __restrict__ X, const float* __restrict__ g,
               const float* __restrict__ be, float* __restrict__ Y) {
    const int row = blockIdx.x * 8 + (threadIdx.x >> 5);
    const int lane = threadIdx.x & 31;
    const float* x = X + (size_t)row * Dm;

    float v[8];
    float s = 0.f, ss = 0.f;
#pragma unroll
    for (int j = 0; j < 8; j++) {
        v[j] = x[lane + 32 * j];
        s += v[j];
        ss += v[j] * v[j];
    }
#pragma unroll
    for (int o = 16; o; o >>= 1) {
        s  += __shfl_xor_sync(0xffffffffu, s, o);
        ss += __shfl_xor_sync(0xffffffffu, ss, o);
    }
    const float mean = s * (1.0f / 256.0f);
    const float var  = ss * (1.0f / 256.0f) - mean * mean;
    const float rs   = rsqrtf(var + 1e-5f);
#pragma unroll
    for (int j = 0; j < 8; j++) {
        const int c = lane + 32 * j;
        Y[(size_t)row * Dm + c] = (v[j] - mean) * rs * g[c] + be[c];
    }
}

// ---------------------------------------------------------------------------
// Launch
// ---------------------------------------------------------------------------
extern "C" void kernel_launch(void* const* d_in, const int* in_sizes, int n_in,
                              void* d_out, int out_size) {
    const float* src  = (const float*)d_in[0];
    const float* pos  = (const float*)d_in[1];
    const float* ref  = (const float*)d_in[2];
    const float* w_value = (const float*)d_in[3];
    const float* b_value = (const float*)d_in[4];
    const float* w_off   = (const float*)d_in[5];
    const float* b_off   = (const float*)d_in[6];
    const float* w_attn  = (const float*)d_in[7];
    const float* b_attn  = (const float*)d_in[8];
    const float* w_out   = (const float*)d_in[9];
    const float* b_out   = (const float*)d_in[10];
    const float* g1  = (const float*)d_in[11];
    const float* be1 = (const float*)d_in[12];
    const float* w1  = (const float*)d_in[13];
    const float* b1  = (const float*)d_in[14];
    const float* w2  = (const float*)d_in[15];
    const float* b2  = (const float*)d_in[16];
    const float* g2  = (const float*)d_in[17];
    const float* be2 = (const float*)d_in[18];
    // d_in[19] spatial_shapes, d_in[20] level_start_index: fixed, hardcoded
    const unsigned char* pad = (const unsigned char*)d_in[21];

    float* out = (float*)d_out;

    float *value, *off, *logits, *a, *res, *x, *h;
    cudaGetSymbolAddress((void**)&value, g_value);
    cudaGetSymbolAddress((void**)&off, g_off);
    cudaGetSymbolAddress((void**)&logits, g_logits);
    cudaGetSymbolAddress((void**)&a, g_a);
    cudaGetSymbolAddress((void**)&res, g_res);
    cudaGetSymbolAddress((void**)&x, g_x);
    cudaGetSymbolAddress((void**)&h, g_h);

    // projections (grid: N/128 x M/128); q = src+pos fused via ADDPOS
    tmma_nt<0, 1><<<dim3(256 / 128, Mrow / 128), 256>>>(src, pos, w_off, b_off, nullptr, nullptr, off, Mrow, 256, Dm);
    tmma_nt<0, 1><<<dim3(128 / 128, Mrow / 128), 256>>>(src, pos, w_attn, b_attn, nullptr, nullptr, logits, Mrow, 128, Dm);
    tmma_nt<2, 0><<<dim3(256 / 128, Mrow / 128), 256>>>(src, nullptr, w_value, b_value, nullptr, pad, value, Mrow, 256, Dm);

    // deformable attention core
    msdeform_kernel<<<Mrow, 256>>>(value, logits, off, ref, a);

    // output projection + residual, LN1
    tmma_nt<3, 0><<<dim3(Dm / 128, Mrow / 128), 256>>>(a, nullptr, w_out, b_out, src, nullptr, res, Mrow, Dm, Dm);
    ln_kernel<<<Mrow / 8, 256>>>(res, g1, be1, x);

    // FFN
    tmma_nt<1, 0><<<dim3(FFm / 128, Mrow / 128), 256>>>(x, nullptr, w1, b1, nullptr, nullptr, h, Mrow, FFm, Dm);
    tmma_nt<3, 0><<<dim3(Dm / 128, Mrow / 128), 256>>>(h, nullptr, w2, b2, x, nullptr, res, Mrow, Dm, FFm);
    ln_kernel<<<Mrow / 8, 256>>>(res, g2, be2, out);
}

// round 14
// speedup vs baseline: 6.6110x; 1.1662x over previous
#include <cuda_runtime.h>
#include <cuda_bf16.h>
#include <math.h>
#include <stdint.h>

// Problem constants (fixed by the reference setup)
#define Bz   4
#define NTOK 5440            // 64*64 + 32*32 + 16*16 + 8*8
#define Dm   256
#define FFm  1024
#define NHh  8
#define NLl  4
#define NPp  4
#define DHd  32
#define Mrow (Bz * NTOK)     // 21760

// ---------------------------------------------------------------------------
// Scratch (device globals; no allocations allowed)
// ---------------------------------------------------------------------------
__device__ float g_value[Mrow * Dm];    // value projection (masked)
__device__ float g_off[Mrow * 256];     // sampling offsets (NH*NL*NP*2 = 256)
__device__ float g_logits[Mrow * 128];  // attention logits (NH*NL*NP = 128)
__device__ float g_a[Mrow * Dm];        // msdeform output
__device__ float g_res[Mrow * Dm];      // pre-LN residual buffer (reused)
__device__ float g_x[Mrow * Dm];        // after LN1
__device__ float g_h[Mrow * FFm];       // FFN hidden

// ---------------------------------------------------------------------------
// Helpers
// ---------------------------------------------------------------------------
__device__ __forceinline__ uint32_t smem_u32(const void* p) {
    return (uint32_t)__cvta_generic_to_shared(p);
}
__device__ __forceinline__ uint32_t f2tf32(float f) {
    uint32_t r;
    asm("cvt.rna.tf32.f32 %0, %1;" : "=r"(r) : "f"(f));
    return r;
}
__device__ __forceinline__ float4 cvt4(float4 v) {
    float4 r;
    r.x = __uint_as_float(f2tf32(v.x));
    r.y = __uint_as_float(f2tf32(v.y));
    r.z = __uint_as_float(f2tf32(v.z));
    r.w = __uint_as_float(f2tf32(v.w));
    return r;
}
__device__ __forceinline__ void mma_tf32(float c[4], const uint32_t a[4], const uint32_t b[2]) {
    asm volatile(
        "mma.sync.aligned.m16n8k8.row.col.f32.tf32.tf32.f32 "
        "{%0,%1,%2,%3}, {%4,%5,%6,%7}, {%8,%9}, {%0,%1,%2,%3};"
        : "+f"(c[0]), "+f"(c[1]), "+f"(c[2]), "+f"(c[3])
        : "r"(a[0]), "r"(a[1]), "r"(a[2]), "r"(a[3]), "r"(b[0]), "r"(b[1]));
}

// ---------------------------------------------------------------------------
// Tensor-core GEMM (NT): C[M,N] = A[M,K] @ W[N,K]^T + bias, fused epilogues.
// tf32 mma.sync m16n8k8, fp32 accumulate. Swapped operands (mma-M = W rows).
// Block 128(m) x 128(n) x BK=16, 8 warps, warp tile 64(n) x 32(m).
// ---------------------------------------------------------------------------
template <int EPI, int ADDPOS>
__global__ __launch_bounds__(256, 2)
void tmma_nt(const float* __restrict__ A, const float* __restrict__ A2,
             const float* __restrict__ W,
             const float* __restrict__ bias, const float* __restrict__ R,
             const unsigned char* __restrict__ mask,
             float* __restrict__ C, int M, int N, int K) {
    constexpr int BK = 16;
    constexpr int PITCH = 20;     // 80 B rows, 16B-aligned, ldmatrix conflict-free
    __shared__ float Xs[128 * PITCH];
    __shared__ float Ws[128 * PITCH];

    const int bm = blockIdx.y * 128;
    const int bn = blockIdx.x * 128;
    const int tid = threadIdx.x;
    const int warp = tid >> 5;
    const int lane = tid & 31;
    const int warp_w = warp >> 2;   // 0..1 -> n-offset 64*warp_w
    const int warp_x = warp & 3;    // 0..3 -> m-offset 32*warp_x

    // global->smem staging: thread loads rows lrow0, lrow0+64; 4 k at lkc.
    const int lrow0 = tid >> 2;         // 0..63
    const int lkc   = (tid & 3) * 4;    // 0,4,8,12

    const float* Aptr  = A + (size_t)(bm + lrow0) * K + lkc;
    const float* A2ptr = ADDPOS ? (A2 + (size_t)(bm + lrow0) * K + lkc) : A;
    const float* Wptr  = W + (size_t)(bn + lrow0) * K + lkc;
    const size_t rowskip = (size_t)64 * K;

    float4 av0 = *(const float4*)(Aptr);
    float4 av1 = *(const float4*)(Aptr + rowskip);
    float4 wv0 = *(const float4*)(Wptr);
    float4 wv1 = *(const float4*)(Wptr + rowskip);
    float4 pv0, pv1;
    if (ADDPOS) {
        pv0 = *(const float4*)(A2ptr);
        pv1 = *(const float4*)(A2ptr + rowskip);
    }

    float acc[4][4][4];
#pragma unroll
    for (int i = 0; i < 4; i++)
#pragma unroll
        for (int j = 0; j < 4; j++)
#pragma unroll
            for (int c = 0; c < 4; c++) acc[i][j][c] = 0.f;

    // A-fragment (W tile) ldmatrix addressing
    const int q = lane >> 3;
    const int ldm_row  = warp_w * 64 + (q & 1) * 8 + (lane & 7);
    const int ldm_koff = (q >> 1) * 4;
    const uint32_t ws_u32 = smem_u32(Ws);
    // B-fragment (X tile) ldmatrix addressing: matrices = (j-block, k-half)
    const int brow = warp_x * 32 + ((q >> 1) << 3) + (lane & 7);
    const int bcol = (q & 1) * 4;
    const uint32_t xs_u32 = smem_u32(Xs) + (uint32_t)((brow * PITCH + bcol) * 4);

    for (int k0 = 0; k0 < K; k0 += BK) {
        // stage both operands as tf32 bits, row-major [row][k]
        {
            float4 a0 = av0, a1 = av1;
            if (ADDPOS) {
                a0.x += pv0.x; a0.y += pv0.y; a0.z += pv0.z; a0.w += pv0.w;
                a1.x += pv1.x; a1.y += pv1.y; a1.z += pv1.z; a1.w += pv1.w;
            }
            *(float4*)&Xs[(size_t)lrow0 * PITCH + lkc]        = cvt4(a0);
            *(float4*)&Xs[(size_t)(lrow0 + 64) * PITCH + lkc] = cvt4(a1);
            *(float4*)&Ws[(size_t)lrow0 * PITCH + lkc]        = cvt4(wv0);
            *(float4*)&Ws[(size_t)(lrow0 + 64) * PITCH + lkc] = cvt4(wv1);
        }
        __syncthreads();

        if (k0 + BK < K) {
            const float* An = Aptr + k0 + BK;
            const float* Wn = Wptr + k0 + BK;
            av0 = *(const float4*)(An);
            av1 = *(const float4*)(An + rowskip);
            wv0 = *(const float4*)(Wn);
            wv1 = *(const float4*)(Wn + rowskip);
            if (ADDPOS) {
                const float* Pn = A2ptr + k0 + BK;
                pv0 = *(const float4*)(Pn);
                pv1 = *(const float4*)(Pn + rowskip);
            }
        }

#pragma unroll
        for (int k8 = 0; k8 < BK; k8 += 8) {
            // A-operand fragments (W tile)
            uint32_t a[4][4];
#pragma unroll
            for (int i = 0; i < 4; i++) {
                uint32_t addr = ws_u32 +
                    (uint32_t)(((ldm_row + i * 16) * PITCH + k8 + ldm_koff) * 4);
                asm volatile(
                    "ldmatrix.sync.aligned.m8n8.x4.shared.b16 {%0,%1,%2,%3}, [%4];"
                    : "=r"(a[i][0]), "=r"(a[i][1]), "=r"(a[i][2]), "=r"(a[i][3])
                    : "r"(addr));
            }
            // B-operand fragments (X tile): 2 x ldmatrix.x4 cover j=0..3
            uint32_t b[4][2];
            {
                uint32_t addr0 = xs_u32 + (uint32_t)(k8 * 4);
                uint32_t addr1 = addr0 + (uint32_t)(16 * PITCH * 4);
                asm volatile(
                    "ldmatrix.sync.aligned.m8n8.x4.shared.b16 {%0,%1,%2,%3}, [%4];"
                    : "=r"(b[0][0]), "=r"(b[0][1]), "=r"(b[1][0]), "=r"(b[1][1])
                    : "r"(addr0));
                asm volatile(
                    "ldmatrix.sync.aligned.m8n8.x4.shared.b16 {%0,%1,%2,%3}, [%4];"
                    : "=r"(b[2][0]), "=r"(b[2][1]), "=r"(b[3][0]), "=r"(b[3][1])
                    : "r"(addr1));
            }

#pragma unroll
            for (int i = 0; i < 4; i++)
#pragma unroll
                for (int j = 0; j < 4; j++)
                    mma_tf32(acc[i][j], a[i], b[j]);
        }
        __syncthreads();
    }

    // epilogue
    const int r4 = lane >> 2;
    const int t4 = lane & 3;
#pragma unroll
    for (int i = 0; i < 4; i++) {
        const int n0g = bn + warp_w * 64 + i * 16 + r4;
        const float bi0 = bias[n0g];
        const float bi1 = bias[n0g + 8];
#pragma unroll
        for (int j = 0; j < 4; j++) {
            const int mb = bm + warp_x * 32 + j * 8 + t4 * 2;
#pragma unroll
            for (int cr = 0; cr < 4; cr++) {
                const int n = n0g + (cr >> 1) * 8;
                const int m = mb + (cr & 1);
                float v = acc[i][j][cr] + ((cr >> 1) ? bi1 : bi0);
                if (EPI == 1) v = fmaxf(v, 0.f);
                if (EPI == 2) { if (mask[m]) v = 0.f; }
                if (EPI == 3) v += R[(size_t)m * N + n];
                C[(size_t)m * N + n] = v;
            }
        }
    }
}

// ---------------------------------------------------------------------------
// Multi-scale deformable attention core (warp-cooperative sample setup).
// Block = one (b, query), 8 warps = 8 heads, lane = channel.
// Lane s (s = lane & 15) computes sample s's 4 clamped corner indices and
// 4 validity-folded weights (attention weight folded in); the 16-sample
// accumulation loop broadcasts them via shfl. Inner body: 8 shfl + 4
// coalesced 128B-aligned LDG + 4 FFMA. No branches.
// ---------------------------------------------------------------------------
__global__ __launch_bounds__(256)
void msdeform_kernel(const float* __restrict__ value,
                     const float* __restrict__ logits,
                     const float* __restrict__ off,
                     const float* __restrict__ ref,
                     float* __restrict__ out) {
    const int row = blockIdx.x;          // b * NTOK + q
    const int h = threadIdx.x >> 5;
    const int lane = threadIdx.x & 31;
    const int b = row / NTOK;
    const int s = lane & 15;

    // softmax over 16 samples of this head (replicated in both warp halves)
    float logit = logits[(size_t)row * 128 + h * 16 + s];
    float mx = logit;
#pragma unroll
    for (int o = 8; o; o >>= 1) mx = fmaxf(mx, __shfl_xor_sync(0xffffffffu, mx, o));
    float e = expf(logit - mx);
    float sm = e;
#pragma unroll
    for (int o = 8; o; o >>= 1) sm += __shfl_xor_sync(0xffffffffu, sm, o);
    const float wn = e / sm;

    // ---- per-lane sample setup (sample s, level l = s>>2) ----
    const int l = s >> 2;
    const int HW = 64 >> l;                    // 64,32,16,8
    const float ox = off[(size_t)row * 256 + (h * 16 + s) * 2 + 0];
    const float oy = off[(size_t)row * 256 + (h * 16 + s) * 2 + 1];
    const float rx = ref[(size_t)row * 8 + l * 2 + 0];
    const float ry = ref[(size_t)row * 8 + l * 2 + 1];

    // pixel coords: (ref + off/W)*W - 0.5 == ref*W + off - 0.5 (square levels)
    const float px = rx * (float)HW + ox - 0.5f;
    const float py = ry * (float)HW + oy - 0.5f;
    const float x0f = floorf(px), y0f = floorf(py);
    const float fx = px - x0f, fy = py - y0f;
    const int x0 = (int)x0f, y0 = (int)y0f;
    const int x1 = x0 + 1, y1 = y0 + 1;

    const bool vx0 = (x0 >= 0) & (x0 < HW);
    const bool vx1 = (x1 >= 0) & (x1 < HW);
    const bool vy0 = (y0 >= 0) & (y0 < HW);
    const bool vy1 = (y1 >= 0) & (y1 < HW);
    const int x0c = min(max(x0, 0), HW - 1);
    const int x1c = min(max(x1, 0), HW - 1);
    const int y0c = min(max(y0, 0), HW - 1);
    const int y1c = min(max(y1, 0), HW - 1);

    // weights: attention weight folded in, zeroed when corner invalid
    float w00 = wn * (1.f - fx) * (1.f - fy); if (!(vx0 & vy0)) w00 = 0.f;
    float w10 = wn * fx * (1.f - fy);         if (!(vx1 & vy0)) w10 = 0.f;
    float w01 = wn * (1.f - fx) * fy;         if (!(vx0 & vy1)) w01 = 0.f;
    float w11 = wn * fx * fy;                 if (!(vx1 & vy1)) w11 = 0.f;

    const int i00 = y0c * HW + x0c;
    const int i10 = y0c * HW + x1c;
    const int i01 = y1c * HW + x0c;
    const int i11 = y1c * HW + x1c;

    // per-level base pointers: value + ((b*NTOK + start)*NH + h)*DH + lane
    const float* base0 = value + ((size_t)b * NTOK) * 256 + h * 32 + lane;

    float acc = 0.f;
#pragma unroll
    for (int s2 = 0; s2 < 16; s2++) {
        constexpr int starts_c[4] = {0, 4096, 5120, 5376};
        const float* bl = base0 + (size_t)starts_c[s2 >> 2] * 256;
        const int j00 = __shfl_sync(0xffffffffu, i00, s2);
        const int j10 = __shfl_sync(0xffffffffu, i10, s2);
        const int j01 = __shfl_sync(0xffffffffu, i01, s2);
        const int j11 = __shfl_sync(0xffffffffu, i11, s2);
        const float u00 = __shfl_sync(0xffffffffu, w00, s2);
        const float u10 = __shfl_sync(0xffffffffu, w10, s2);
        const float u01 = __shfl_sync(0xffffffffu, w01, s2);
        const float u11 = __shfl_sync(0xffffffffu, w11, s2);
        acc += u00 * bl[(size_t)j00 * 256] + u10 * bl[(size_t)j10 * 256]
             + u01 * bl[(size_t)j01 * 256] + u11 * bl[(size_t)j11 * 256];
    }
    out[(size_t)row * Dm + h * DHd + lane] = acc;
}

// ---------------------------------------------------------------------------
// LayerNorm over last dim (256). One warp per row, 8 rows per block.
// ---------------------------------------------------------------------------
__global__ __launch_bounds__(256)
void ln_kernel(const float* __restrict__ X, const float* __restrict__ g,
               const float* __restrict__ be, float* __restrict__ Y) {
    const int row = blockIdx.x * 8 + (threadIdx.x >> 5);
    const int lane = threadIdx.x & 31;
    const float* x = X + (size_t)row * Dm;

    float v[8];
    float s = 0.f, ss = 0.f;
#pragma unroll
    for (int j = 0; j < 8; j++) {
        v[j] = x[lane + 32 * j];
        s += v[j];
        ss += v[j] * v[j];
    }
#pragma unroll
    for (int o = 16; o; o >>= 1) {
        s  += __shfl_xor_sync(0xffffffffu, s, o);
        ss += __shfl_xor_sync(0xffffffffu, ss, o);
    }
    const float mean = s * (1.0f / 256.0f);
    const float var  = ss * (1.0f / 256.0f) - mean * mean;
    const float rs   = rsqrtf(var + 1e-5f);
#pragma unroll
    for (int j = 0; j < 8; j++) {
        const int c = lane + 32 * j;
        Y[(size_t)row * Dm + c] = (v[j] - mean) * rs * g[c] + be[c];
    }
}

// ---------------------------------------------------------------------------
// Launch
// ---------------------------------------------------------------------------
extern "C" void kernel_launch(void* const* d_in, const int* in_sizes, int n_in,
                              void* d_out, int out_size) {
    const float* src  = (const float*)d_in[0];
    const float* pos  = (const float*)d_in[1];
    const float* ref  = (const float*)d_in[2];
    const float* w_value = (const float*)d_in[3];
    const float* b_value = (const float*)d_in[4];
    const float* w_off   = (const float*)d_in[5];
    const float* b_off   = (const float*)d_in[6];
    const float* w_attn  = (const float*)d_in[7];
    const float* b_attn  = (const float*)d_in[8];
    const float* w_out   = (const float*)d_in[9];
    const float* b_out   = (const float*)d_in[10];
    const float* g1  = (const float*)d_in[11];
    const float* be1 = (const float*)d_in[12];
    const float* w1  = (const float*)d_in[13];
    const float* b1  = (const float*)d_in[14];
    const float* w2  = (const float*)d_in[15];
    const float* b2  = (const float*)d_in[16];
    const float* g2  = (const float*)d_in[17];
    const float* be2 = (const float*)d_in[18];
    // d_in[19] spatial_shapes, d_in[20] level_start_index: fixed, hardcoded
    const unsigned char* pad = (const unsigned char*)d_in[21];

    float* out = (float*)d_out;

    float *value, *off, *logits, *a, *res, *x, *h;
    cudaGetSymbolAddress((void**)&value, g_value);
    cudaGetSymbolAddress((void**)&off, g_off);
    cudaGetSymbolAddress((void**)&logits, g_logits);
    cudaGetSymbolAddress((void**)&a, g_a);
    cudaGetSymbolAddress((void**)&res, g_res);
    cudaGetSymbolAddress((void**)&x, g_x);
    cudaGetSymbolAddress((void**)&h, g_h);

    // projections (grid: N/128 x M/128); q = src+pos fused via ADDPOS
    tmma_nt<0, 1><<<dim3(256 / 128, Mrow / 128), 256>>>(src, pos, w_off, b_off, nullptr, nullptr, off, Mrow, 256, Dm);
    tmma_nt<0, 1><<<dim3(128 / 128, Mrow / 128), 256>>>(src, pos, w_attn, b_attn, nullptr, nullptr, logits, Mrow, 128, Dm);
    tmma_nt<2, 0><<<dim3(256 / 128, Mrow / 128), 256>>>(src, nullptr, w_value, b_value, nullptr, pad, value, Mrow, 256, Dm);

    // deformable attention core
    msdeform_kernel<<<Mrow, 256>>>(value, logits, off, ref, a);

    // output projection + residual, LN1
    tmma_nt<3, 0><<<dim3(Dm / 128, Mrow / 128), 256>>>(a, nullptr, w_out, b_out, src, nullptr, res, Mrow, Dm, Dm);
    ln_kernel<<<Mrow / 8, 256>>>(res, g1, be1, x);

    // FFN
    tmma_nt<1, 0><<<dim3(FFm / 128, Mrow / 128), 256>>>(x, nullptr, w1, b1, nullptr, nullptr, h, Mrow, FFm, Dm);
    tmma_nt<3, 0><<<dim3(Dm / 128, Mrow / 128), 256>>>(h, nullptr, w2, b2, x, nullptr, res, Mrow, Dm, FFm);
    ln_kernel<<<Mrow / 8, 256>>>(res, g2, be2, out);
}

// round 17
// speedup vs baseline: 6.8311x; 1.0333x over previous
#include <cuda_runtime.h>
#include <cuda_bf16.h>
#include <math.h>
#include <stdint.h>

// Problem constants (fixed by the reference setup)
#define Bz   4
#define NTOK 5440            // 64*64 + 32*32 + 16*16 + 8*8
#define Dm   256
#define FFm  1024
#define NHh  8
#define NLl  4
#define NPp  4
#define DHd  32
#define Mrow (Bz * NTOK)     // 21760

// ---------------------------------------------------------------------------
// Scratch (device globals; no allocations allowed)
// ---------------------------------------------------------------------------
__device__ __nv_bfloat16 g_value_bf[Mrow * Dm];  // value projection (masked, bf16)
__device__ float g_off[Mrow * 256];     // sampling offsets (NH*NL*NP*2 = 256)
__device__ float g_logits[Mrow * 128];  // attention logits (NH*NL*NP = 128)
__device__ float g_a[Mrow * Dm];        // msdeform output
__device__ float g_res[Mrow * Dm];      // pre-LN residual buffer (reused)
__device__ float g_x[Mrow * Dm];        // after LN1
__device__ float g_h[Mrow * FFm];       // FFN hidden

// ---------------------------------------------------------------------------
// Helpers
// ---------------------------------------------------------------------------
__device__ __forceinline__ uint32_t smem_u32(const void* p) {
    return (uint32_t)__cvta_generic_to_shared(p);
}
__device__ __forceinline__ uint32_t f2tf32(float f) {
    uint32_t r;
    asm("cvt.rna.tf32.f32 %0, %1;" : "=r"(r) : "f"(f));
    return r;
}
__device__ __forceinline__ float4 cvt4(float4 v) {
    float4 r;
    r.x = __uint_as_float(f2tf32(v.x));
    r.y = __uint_as_float(f2tf32(v.y));
    r.z = __uint_as_float(f2tf32(v.z));
    r.w = __uint_as_float(f2tf32(v.w));
    return r;
}
__device__ __forceinline__ void mma_tf32(float c[4], const uint32_t a[4], const uint32_t b[2]) {
    asm volatile(
        "mma.sync.aligned.m16n8k8.row.col.f32.tf32.tf32.f32 "
        "{%0,%1,%2,%3}, {%4,%5,%6,%7}, {%8,%9}, {%0,%1,%2,%3};"
        : "+f"(c[0]), "+f"(c[1]), "+f"(c[2]), "+f"(c[3])
        : "r"(a[0]), "r"(a[1]), "r"(a[2]), "r"(a[3]), "r"(b[0]), "r"(b[1]));
}

// ---------------------------------------------------------------------------
// Tensor-core GEMM (NT): C[M,N] = A[M,K] @ W[N,K]^T + bias, fused epilogues.
// tf32 mma.sync m16n8k8, fp32 accumulate. Swapped operands (mma-M = W rows).
// Block 128(m) x 128(n) x BK=16, 8 warps, warp tile 64(n) x 32(m).
// DOUBLE-BUFFERED smem: stage tile k+1 while computing tile k; one
// __syncthreads per k-tile.
// EPI: 0=plain 1=relu 2=zero-where-mask 3=add residual. OUTBF: bf16 output.
// ---------------------------------------------------------------------------
template <int EPI, int ADDPOS, int OUTBF>
__global__ __launch_bounds__(256, 2)
void tmma_nt(const float* __restrict__ A, const float* __restrict__ A2,
             const float* __restrict__ W,
             const float* __restrict__ bias, const float* __restrict__ R,
             const unsigned char* __restrict__ mask,
             float* __restrict__ C, int M, int N, int K) {
    constexpr int BK = 16;
    constexpr int PITCH = 20;          // 80 B rows, 16B-aligned, ldmatrix conflict-free
    constexpr int BUFELEMS = 128 * PITCH;
    __shared__ float Xs[2 * BUFELEMS];
    __shared__ float Ws[2 * BUFELEMS];

    const int bm = blockIdx.y * 128;
    const int bn = blockIdx.x * 128;
    const int tid = threadIdx.x;
    const int warp = tid >> 5;
    const int lane = tid & 31;
    const int warp_w = warp >> 2;   // 0..1 -> n-offset 64*warp_w
    const int warp_x = warp & 3;    // 0..3 -> m-offset 32*warp_x

    // global->smem staging: thread loads rows lrow0, lrow0+64; 4 k at lkc.
    const int lrow0 = tid >> 2;         // 0..63
    const int lkc   = (tid & 3) * 4;    // 0,4,8,12

    const float* Aptr  = A + (size_t)(bm + lrow0) * K + lkc;
    const float* A2ptr = ADDPOS ? (A2 + (size_t)(bm + lrow0) * K + lkc) : A;
    const float* Wptr  = W + (size_t)(bn + lrow0) * K + lkc;
    const size_t rowskip = (size_t)64 * K;

    float4 av0 = *(const float4*)(Aptr);
    float4 av1 = *(const float4*)(Aptr + rowskip);
    float4 wv0 = *(const float4*)(Wptr);
    float4 wv1 = *(const float4*)(Wptr + rowskip);
    float4 pv0, pv1;
    if (ADDPOS) {
        pv0 = *(const float4*)(A2ptr);
        pv1 = *(const float4*)(A2ptr + rowskip);
    }

    float acc[4][4][4];
#pragma unroll
    for (int i = 0; i < 4; i++)
#pragma unroll
        for (int j = 0; j < 4; j++)
#pragma unroll
            for (int c = 0; c < 4; c++) acc[i][j][c] = 0.f;

    // A-fragment (W tile) ldmatrix addressing
    const int q = lane >> 3;
    const int ldm_row  = warp_w * 64 + (q & 1) * 8 + (lane & 7);
    const int ldm_koff = (q >> 1) * 4;
    const uint32_t ws_u32 = smem_u32(Ws);
    // B-fragment (X tile) ldmatrix addressing: matrices = (j-block, k-half)
    const int brow = warp_x * 32 + ((q >> 1) << 3) + (lane & 7);
    const int bcol = (q & 1) * 4;
    const uint32_t xs_u32 = smem_u32(Xs) + (uint32_t)((brow * PITCH + bcol) * 4);
    const uint32_t BUFBYTES = (uint32_t)(BUFELEMS * 4);

    // stage tile 0 into buffer 0
    {
        float4 a0 = av0, a1 = av1;
        if (ADDPOS) {
            a0.x += pv0.x; a0.y += pv0.y; a0.z += pv0.z; a0.w += pv0.w;
            a1.x += pv1.x; a1.y += pv1.y; a1.z += pv1.z; a1.w += pv1.w;
        }
        *(float4*)&Xs[(size_t)lrow0 * PITCH + lkc]        = cvt4(a0);
        *(float4*)&Xs[(size_t)(lrow0 + 64) * PITCH + lkc] = cvt4(a1);
        *(float4*)&Ws[(size_t)lrow0 * PITCH + lkc]        = cvt4(wv0);
        *(float4*)&Ws[(size_t)(lrow0 + 64) * PITCH + lkc] = cvt4(wv1);
    }
    __syncthreads();

    const int nk = K / BK;
    for (int kt = 0; kt < nk; kt++) {
        const int cur = kt & 1;
        const uint32_t cofs = cur ? BUFBYTES : 0u;

        // prefetch tile kt+1 into registers (hides GMEM latency behind compute)
        if (kt + 1 < nk) {
            const int k0n = (kt + 1) * BK;
            const float* An = Aptr + k0n;
            const float* Wn = Wptr + k0n;
            av0 = *(const float4*)(An);
            av1 = *(const float4*)(An + rowskip);
            wv0 = *(const float4*)(Wn);
            wv1 = *(const float4*)(Wn + rowskip);
            if (ADDPOS) {
                const float* Pn = A2ptr + k0n;
                pv0 = *(const float4*)(Pn);
                pv1 = *(const float4*)(Pn + rowskip);
            }
        }

        // compute from buffer cur
#pragma unroll
        for (int k8 = 0; k8 < BK; k8 += 8) {
            uint32_t a[4][4];
#pragma unroll
            for (int i = 0; i < 4; i++) {
                uint32_t addr = ws_u32 + cofs +
                    (uint32_t)(((ldm_row + i * 16) * PITCH + k8 + ldm_koff) * 4);
                asm volatile(
                    "ldmatrix.sync.aligned.m8n8.x4.shared.b16 {%0,%1,%2,%3}, [%4];"
                    : "=r"(a[i][0]), "=r"(a[i][1]), "=r"(a[i][2]), "=r"(a[i][3])
                    : "r"(addr));
            }
            uint32_t b[4][2];
            {
                uint32_t addr0 = xs_u32 + cofs + (uint32_t)(k8 * 4);
                uint32_t addr1 = addr0 + (uint32_t)(16 * PITCH * 4);
                asm volatile(
                    "ldmatrix.sync.aligned.m8n8.x4.shared.b16 {%0,%1,%2,%3}, [%4];"
                    : "=r"(b[0][0]), "=r"(b[0][1]), "=r"(b[1][0]), "=r"(b[1][1])
                    : "r"(addr0));
                asm volatile(
                    "ldmatrix.sync.aligned.m8n8.x4.shared.b16 {%0,%1,%2,%3}, [%4];"
                    : "=r"(b[2][0]), "=r"(b[2][1]), "=r"(b[3][0]), "=r"(b[3][1])
                    : "r"(addr1));
            }
#pragma unroll
            for (int i = 0; i < 4; i++)
#pragma unroll
                for (int j = 0; j < 4; j++)
                    mma_tf32(acc[i][j], a[i], b[j]);
        }

        // stage tile kt+1 into the other buffer
        if (kt + 1 < nk) {
            const int nxt = (cur ^ 1) * BUFELEMS;
            float4 a0 = av0, a1 = av1;
            if (ADDPOS) {
                a0.x += pv0.x; a0.y += pv0.y; a0.z += pv0.z; a0.w += pv0.w;
                a1.x += pv1.x; a1.y += pv1.y; a1.z += pv1.z; a1.w += pv1.w;
            }
            *(float4*)&Xs[nxt + (size_t)lrow0 * PITCH + lkc]        = cvt4(a0);
            *(float4*)&Xs[nxt + (size_t)(lrow0 + 64) * PITCH + lkc] = cvt4(a1);
            *(float4*)&Ws[nxt + (size_t)lrow0 * PITCH + lkc]        = cvt4(wv0);
            *(float4*)&Ws[nxt + (size_t)(lrow0 + 64) * PITCH + lkc] = cvt4(wv1);
        }
        __syncthreads();
    }

    // epilogue: C[m][n] = acc + bias[n] (+EPI). c-frag: c0:(r,2t) c1:(r,2t+1)
    // c2:(r+8,2t) c3:(r+8,2t+1) in (n,m)-space.
    const int r4 = lane >> 2;
    const int t4 = lane & 3;
    __nv_bfloat16* Cb = reinterpret_cast<__nv_bfloat16*>(C);
#pragma unroll
    for (int i = 0; i < 4; i++) {
        const int n0g = bn + warp_w * 64 + i * 16 + r4;
        const float bi0 = bias[n0g];
        const float bi1 = bias[n0g + 8];
#pragma unroll
        for (int j = 0; j < 4; j++) {
            const int mb = bm + warp_x * 32 + j * 8 + t4 * 2;
#pragma unroll
            for (int cr = 0; cr < 4; cr++) {
                const int n = n0g + (cr >> 1) * 8;
                const int m = mb + (cr & 1);
                float v = acc[i][j][cr] + ((cr >> 1) ? bi1 : bi0);
                if (EPI == 1) v = fmaxf(v, 0.f);
                if (EPI == 2) { if (mask[m]) v = 0.f; }
                if (EPI == 3) v += R[(size_t)m * N + n];
                if (OUTBF) Cb[(size_t)m * N + n] = __float2bfloat16(v);
                else       C[(size_t)m * N + n] = v;
            }
        }
    }
}

// ---------------------------------------------------------------------------
// Multi-scale deformable attention core (warp-cooperative sample setup).
// value is bf16: each corner gather touches 64 B (2 sectors) instead of
// 128 B (4 sectors), halving the L1-sector traffic that bounds this kernel.
// ---------------------------------------------------------------------------
__global__ __launch_bounds__(256)
void msdeform_kernel(const __nv_bfloat16* __restrict__ value,
                     const float* __restrict__ logits,
                     const float* __restrict__ off,
                     const float* __restrict__ ref,
                     float* __restrict__ out) {
    const int row = blockIdx.x;          // b * NTOK + q
    const int h = threadIdx.x >> 5;
    const int lane = threadIdx.x & 31;
    const int b = row / NTOK;
    const int s = lane & 15;

    // softmax over 16 samples of this head (replicated in both warp halves)
    float logit = logits[(size_t)row * 128 + h * 16 + s];
    float mx = logit;
#pragma unroll
    for (int o = 8; o; o >>= 1) mx = fmaxf(mx, __shfl_xor_sync(0xffffffffu, mx, o));
    float e = expf(logit - mx);
    float sm = e;
#pragma unroll
    for (int o = 8; o; o >>= 1) sm += __shfl_xor_sync(0xffffffffu, sm, o);
    const float wn = e / sm;

    // ---- per-lane sample setup (sample s, level l = s>>2) ----
    const int l = s >> 2;
    const int HW = 64 >> l;                    // 64,32,16,8
    const float ox = off[(size_t)row * 256 + (h * 16 + s) * 2 + 0];
    const float oy = off[(size_t)row * 256 + (h * 16 + s) * 2 + 1];
    const float rx = ref[(size_t)row * 8 + l * 2 + 0];
    const float ry = ref[(size_t)row * 8 + l * 2 + 1];

    // pixel coords: (ref + off/W)*W - 0.5 == ref*W + off - 0.5 (square levels)
    const float px = rx * (float)HW + ox - 0.5f;
    const float py = ry * (float)HW + oy - 0.5f;
    const float x0f = floorf(px), y0f = floorf(py);
    const float fx = px - x0f, fy = py - y0f;
    const int x0 = (int)x0f, y0 = (int)y0f;
    const int x1 = x0 + 1, y1 = y0 + 1;

    const bool vx0 = (x0 >= 0) & (x0 < HW);
    const bool vx1 = (x1 >= 0) & (x1 < HW);
    const bool vy0 = (y0 >= 0) & (y0 < HW);
    const bool vy1 = (y1 >= 0) & (y1 < HW);
    const int x0c = min(max(x0, 0), HW - 1);
    const int x1c = min(max(x1, 0), HW - 1);
    const int y0c = min(max(y0, 0), HW - 1);
    const int y1c = min(max(y1, 0), HW - 1);

    // weights: attention weight folded in, zeroed when corner invalid
    float w00 = wn * (1.f - fx) * (1.f - fy); if (!(vx0 & vy0)) w00 = 0.f;
    float w10 = wn * fx * (1.f - fy);         if (!(vx1 & vy0)) w10 = 0.f;
    float w01 = wn * (1.f - fx) * fy;         if (!(vx0 & vy1)) w01 = 0.f;
    float w11 = wn * fx * fy;                 if (!(vx1 & vy1)) w11 = 0.f;

    const int i00 = y0c * HW + x0c;
    const int i10 = y0c * HW + x1c;
    const int i01 = y1c * HW + x0c;
    const int i11 = y1c * HW + x1c;

    // per-level base pointers: value + ((b*NTOK + start)*NH + h)*DH + lane
    const __nv_bfloat16* base0 = value + ((size_t)b * NTOK) * 256 + h * 32 + lane;

    float acc = 0.f;
#pragma unroll
    for (int s2 = 0; s2 < 16; s2++) {
        constexpr int starts_c[4] = {0, 4096, 5120, 5376};
        const __nv_bfloat16* bl = base0 + (size_t)starts_c[s2 >> 2] * 256;
        const int j00 = __shfl_sync(0xffffffffu, i00, s2);
        const int j10 = __shfl_sync(0xffffffffu, i10, s2);
        const int j01 = __shfl_sync(0xffffffffu, i01, s2);
        const int j11 = __shfl_sync(0xffffffffu, i11, s2);
        const float u00 = __shfl_sync(0xffffffffu, w00, s2);
        const float u10 = __shfl_sync(0xffffffffu, w10, s2);
        const float u01 = __shfl_sync(0xffffffffu, w01, s2);
        const float u11 = __shfl_sync(0xffffffffu, w11, s2);
        acc += u00 * __bfloat162float(bl[(size_t)j00 * 256])
             + u10 * __bfloat162float(bl[(size_t)j10 * 256])
             + u01 * __bfloat162float(bl[(size_t)j01 * 256])
             + u11 * __bfloat162float(bl[(size_t)j11 * 256]);
    }
    out[(size_t)row * Dm + h * DHd + lane] = acc;
}

// ---------------------------------------------------------------------------
// LayerNorm over last dim (256). One warp per row, 8 rows per block.
// ---------------------------------------------------------------------------
__global__ __launch_bounds__(256)
void ln_kernel(const float* __restrict__ X, const float* __restrict__ g,
               const float* __restrict__ be, float* __restrict__ Y) {
    const int row = blockIdx.x * 8 + (threadIdx.x >> 5);
    const int lane = threadIdx.x & 31;
    const float* x = X + (size_t)row * Dm;

    float v[8];
    float s = 0.f, ss = 0.f;
#pragma unroll
    for (int j = 0; j < 8; j++) {
        v[j] = x[lane + 32 * j];
        s += v[j];
        ss += v[j] * v[j];
    }
#pragma unroll
    for (int o = 16; o; o >>= 1) {
        s  += __shfl_xor_sync(0xffffffffu, s, o);
        ss += __shfl_xor_sync(0xffffffffu, ss, o);
    }
    const float mean = s * (1.0f / 256.0f);
    const float var  = ss * (1.0f / 256.0f) - mean * mean;
    const float rs   = rsqrtf(var + 1e-5f);
#pragma unroll
    for (int j = 0; j < 8; j++) {
        const int c = lane + 32 * j;
        Y[(size_t)row * Dm + c] = (v[j] - mean) * rs * g[c] + be[c];
    }
}

// ---------------------------------------------------------------------------
// Launch
// ---------------------------------------------------------------------------
extern "C" void kernel_launch(void* const* d_in, const int* in_sizes, int n_in,
                              void* d_out, int out_size) {
    const float* src  = (const float*)d_in[0];
    const float* pos  = (const float*)d_in[1];
    const float* ref  = (const float*)d_in[2];
    const float* w_value = (const float*)d_in[3];
    const float* b_value = (const float*)d_in[4];
    const float* w_off   = (const float*)d_in[5];
    const float* b_off   = (const float*)d_in[6];
    const float* w_attn  = (const float*)d_in[7];
    const float* b_attn  = (const float*)d_in[8];
    const float* w_out   = (const float*)d_in[9];
    const float* b_out   = (const float*)d_in[10];
    const float* g1  = (const float*)d_in[11];
    const float* be1 = (const float*)d_in[12];
    const float* w1  = (const float*)d_in[13];
    const float* b1  = (const float*)d_in[14];
    const float* w2  = (const float*)d_in[15];
    const float* b2  = (const float*)d_in[16];
    const float* g2  = (const float*)d_in[17];
    const float* be2 = (const float*)d_in[18];
    // d_in[19] spatial_shapes, d_in[20] level_start_index: fixed, hardcoded
    const unsigned char* pad = (const unsigned char*)d_in[21];

    float* out = (float*)d_out;

    __nv_bfloat16* value_bf;
    float *off, *logits, *a, *res, *x, *h;
    cudaGetSymbolAddress((void**)&value_bf, g_value_bf);
    cudaGetSymbolAddress((void**)&off, g_off);
    cudaGetSymbolAddress((void**)&logits, g_logits);
    cudaGetSymbolAddress((void**)&a, g_a);
    cudaGetSymbolAddress((void**)&res, g_res);
    cudaGetSymbolAddress((void**)&x, g_x);
    cudaGetSymbolAddress((void**)&h, g_h);

    // projections (grid: N/128 x M/128); q = src+pos fused via ADDPOS
    tmma_nt<0, 1, 0><<<dim3(256 / 128, Mrow / 128), 256>>>(src, pos, w_off, b_off, nullptr, nullptr, off, Mrow, 256, Dm);
    tmma_nt<0, 1, 0><<<dim3(128 / 128, Mrow / 128), 256>>>(src, pos, w_attn, b_attn, nullptr, nullptr, logits, Mrow, 128, Dm);
    tmma_nt<2, 0, 1><<<dim3(256 / 128, Mrow / 128), 256>>>(src, nullptr, w_value, b_value, nullptr, pad, (float*)value_bf, Mrow, 256, Dm);

    // deformable attention core
    msdeform_kernel<<<Mrow, 256>>>(value_bf, logits, off, ref, a);

    // output projection + residual, LN1
    tmma_nt<3, 0, 0><<<dim3(Dm / 128, Mrow / 128), 256>>>(a, nullptr, w_out, b_out, src, nullptr, res, Mrow, Dm, Dm);
    ln_kernel<<<Mrow / 8, 256>>>(res, g1, be1, x);

    // FFN
    tmma_nt<1, 0, 0><<<dim3(FFm / 128, Mrow / 128), 256>>>(x, nullptr, w1, b1, nullptr, nullptr, h, Mrow, FFm, Dm);
    tmma_nt<3, 0, 0><<<dim3(Dm / 128, Mrow / 128), 256>>>(h, nullptr, w2, b2, x, nullptr, res, Mrow, Dm, FFm);
    ln_kernel<<<Mrow / 8, 256>>>(res, g2, be2, out);
}